// round 1
// baseline (speedup 1.0000x reference)
#include <cuda_runtime.h>
#include <math.h>

// Problem shapes (fixed for this benchmark)
#define N_ROWS   2048
#define DIM      512
#define NQ       3
#define KQ       8192
#define QK       (NQ * KQ)        // 24576
#define NCLS     16

#define BM 128
#define BN 128
#define BK 16
#define NKTILES (QK / BN)         // 192

// ---------------- scratch (static device globals; no allocation) -----------
__device__ float g_xinv[N_ROWS];
__device__ float g_qinv[QK];
__device__ float g_pt[NKTILES * N_ROWS];   // per-ktile partial totals
__device__ float g_pm[NKTILES * N_ROWS];   // per-ktile partial masked sums
__device__ int   g_hist[NCLS];
__device__ int   g_meta[4];                // [0]=targets is64, [1]=q_targets is64, [2]=order

__device__ __forceinline__ int load_tgt(const void* p, int i, int is64) {
    if (is64) return (int)((const long long*)p)[i];
    return ((const int*)p)[i];
}

// ---------------- k_init: dtype detection + order + hist zero --------------
__global__ void k_init(const void* targets, const void* q_targets, const void* order_p) {
    int t = threadIdx.x;  // blockDim = 32
    // targets: if int64, every odd dword is 0 (values < 16). Probe 32 odd dwords.
    unsigned v = ((const unsigned*)targets)[2 * t + 1];
    unsigned any = __ballot_sync(0xffffffffu, v != 0u);
    if (t == 0) g_meta[0] = (any == 0u) ? 1 : 0;
    unsigned w = ((const unsigned*)q_targets)[2 * t + 1];
    unsigned anyq = __ballot_sync(0xffffffffu, w != 0u);
    if (t == 0) g_meta[1] = (anyq == 0u) ? 1 : 0;
    if (t == 0) g_meta[2] = ((const int*)order_p)[0];  // low dword valid for i32/i64
    if (t < NCLS) g_hist[t] = 0;
}

// ---------------- k_norms: inverse L2 norms --------------------------------
__global__ void k_norms(const float* __restrict__ x, const float* __restrict__ q) {
    int warp = (blockIdx.x * blockDim.x + threadIdx.x) >> 5;
    int lane = threadIdx.x & 31;
    if (warp >= N_ROWS + QK) return;
    const float* src = (warp < N_ROWS) ? (x + (size_t)warp * DIM)
                                       : (q + (size_t)(warp - N_ROWS) * DIM);
    float s = 0.f;
    #pragma unroll
    for (int c = 0; c < DIM / 32; c++) {
        float v = src[lane + c * 32];
        s += v * v;
    }
    #pragma unroll
    for (int o = 16; o > 0; o >>= 1) s += __shfl_xor_sync(0xffffffffu, s, o);
    if (lane == 0) {
        float inv = 1.f / fmaxf(sqrtf(s), 1e-12f);
        if (warp < N_ROWS) g_xinv[warp] = inv;
        else               g_qinv[warp - N_ROWS] = inv;
    }
}

// ---------------- k_hist: class histogram of q_targets[order] --------------
__global__ void k_hist(const void* q_targets) {
    int i = blockIdx.x * blockDim.x + threadIdx.x;
    if (i >= KQ) return;
    int v = load_tgt(q_targets, g_meta[2] * KQ + i, g_meta[1]);
    atomicAdd(&g_hist[v], 1);
}

// ---------------- k_main: fused tiled GEMM + exp + row partial sums --------
__global__ void __launch_bounds__(256, 2)
k_main(const float* __restrict__ x, const float* __restrict__ q,
       const void* __restrict__ targets, const void* __restrict__ q_targets) {
    __shared__ float As[BK][BM];
    __shared__ float Bs[BK][BN];
    __shared__ int   qt_s[BN];

    const int tid = threadIdx.x;
    const int tx = tid & 15;       // 16 cols of threads
    const int ty = tid >> 4;       // 16 rows of threads
    const int i0 = blockIdx.y * BM;
    const int j0 = blockIdx.x * BN;

    const int order   = g_meta[2];
    const int is64t   = g_meta[0];
    const int is64q   = g_meta[1];
    const bool otile  = (j0 / KQ) == order;

    if (otile && tid < BN) qt_s[tid] = load_tgt(q_targets, j0 + tid, is64q);

    float acc[8][8];
    #pragma unroll
    for (int r = 0; r < 8; r++)
        #pragma unroll
        for (int c = 0; c < 8; c++) acc[r][c] = 0.f;

    for (int k0 = 0; k0 < DIM; k0 += BK) {
        // Load 128x16 tiles of A and B (512 float4 each; 2 per thread)
        #pragma unroll
        for (int l = 0; l < 2; l++) {
            int idx = tid + l * 256;           // float4 index 0..511
            int row = idx >> 2;                // 0..127
            int c4  = (idx & 3) << 2;          // 0,4,8,12
            float4 va = *(const float4*)(x + (size_t)(i0 + row) * DIM + k0 + c4);
            As[c4 + 0][row] = va.x; As[c4 + 1][row] = va.y;
            As[c4 + 2][row] = va.z; As[c4 + 3][row] = va.w;
            float4 vb = *(const float4*)(q + (size_t)(j0 + row) * DIM + k0 + c4);
            Bs[c4 + 0][row] = vb.x; Bs[c4 + 1][row] = vb.y;
            Bs[c4 + 2][row] = vb.z; Bs[c4 + 3][row] = vb.w;
        }
        __syncthreads();
        #pragma unroll
        for (int kk = 0; kk < BK; kk++) {
            float a[8], b[8];
            *(float4*)(a)     = *(const float4*)&As[kk][ty * 8];
            *(float4*)(a + 4) = *(const float4*)&As[kk][ty * 8 + 4];
            *(float4*)(b)     = *(const float4*)&Bs[kk][tx * 8];
            *(float4*)(b + 4) = *(const float4*)&Bs[kk][tx * 8 + 4];
            #pragma unroll
            for (int r = 0; r < 8; r++)
                #pragma unroll
                for (int c = 0; c < 8; c++) acc[r][c] = fmaf(a[r], b[c], acc[r][c]);
        }
        __syncthreads();
    }

    // Epilogue: scale, exp, per-row (total, masked) partial sums
    float xin[8]; int tg[8]; float qjn[8];
    #pragma unroll
    for (int r = 0; r < 8; r++) {
        xin[r] = g_xinv[i0 + ty * 8 + r];
        tg[r]  = load_tgt(targets, i0 + ty * 8 + r, is64t);
    }
    #pragma unroll
    for (int c = 0; c < 8; c++) qjn[c] = g_qinv[j0 + tx * 8 + c];

    #pragma unroll
    for (int r = 0; r < 8; r++) {
        float srow = 0.f, mrow = 0.f;
        #pragma unroll
        for (int c = 0; c < 8; c++) {
            float sim = acc[r][c] * xin[r] * qjn[c];
            float e = __expf(fmaf(4.f, sim, -4.f));
            srow += e;
            if (otile && qt_s[tx * 8 + c] == tg[r]) mrow += e;
        }
        // reduce across the 16 tx-lanes (xor<16 stays within each 16-lane half)
        #pragma unroll
        for (int o = 1; o < 16; o <<= 1) {
            srow += __shfl_xor_sync(0xffffffffu, srow, o);
            mrow += __shfl_xor_sync(0xffffffffu, mrow, o);
        }
        if (tx == 0) {
            int i = i0 + ty * 8 + r;
            g_pt[blockIdx.x * N_ROWS + i] = srow;
            g_pm[blockIdx.x * N_ROWS + i] = mrow;
        }
    }
}

// ---------------- k_final: deterministic reduction to scalar loss ----------
__global__ void k_final(float* __restrict__ out, const void* __restrict__ targets) {
    __shared__ float red[1024];
    int tid = threadIdx.x;  // blockDim = 1024
    float local = 0.f;
    for (int i = tid; i < N_ROWS; i += 1024) {
        float tot = 0.f, msk = 0.f;
        for (int t = 0; t < NKTILES; t++) {
            tot += g_pt[t * N_ROWS + i];
            msk += g_pm[t * N_ROWS + i];
        }
        int tg = load_tgt(targets, i, g_meta[0]);
        float cnt = (float)(QK - g_hist[tg]);
        local += logf((tot - msk) / cnt);
    }
    red[tid] = local;
    __syncthreads();
    for (int s = 512; s > 0; s >>= 1) {
        if (tid < s) red[tid] += red[tid + s];
        __syncthreads();
    }
    if (tid == 0) out[0] = red[0] / (float)N_ROWS;
}

// ---------------- launch ----------------------------------------------------
extern "C" void kernel_launch(void* const* d_in, const int* in_sizes, int n_in,
                              void* d_out, int out_size) {
    const float* x       = (const float*)d_in[0];
    const float* q       = (const float*)d_in[1];
    const void*  targets = d_in[2];
    const void*  q_tgts  = d_in[3];
    const void*  order_p = d_in[4];

    k_init<<<1, 32>>>(targets, q_tgts, order_p);
    {
        int total_warps = N_ROWS + QK;              // 26624
        int blocks = (total_warps + 7) / 8;         // 8 warps/block
        k_norms<<<blocks, 256>>>(x, q);
    }
    k_hist<<<(KQ + 255) / 256, 256>>>(q_tgts);
    dim3 grid(NKTILES, N_ROWS / BM);                // 192 x 16
    k_main<<<grid, 256>>>(x, q, targets, q_tgts);
    k_final<<<1, 1024>>>((float*)d_out, targets);
}

// round 7
// speedup vs baseline: 5.2479x; 5.2479x over previous
#include <cuda_runtime.h>
#include <cuda_bf16.h>
#include <math.h>
#include <stdint.h>

// ---------------- problem shapes ----------------
#define N_ROWS   2048
#define DIM      512
#define NQ       3
#define KQ       8192
#define QK       (NQ * KQ)        // 24576
#define NCLS     16

// ---------------- GEMM tiling -------------------
#define BM   128                  // x rows per CTA
#define BN   256                  // q rows per CTA
#define BK   32                   // bf16 K per stage
#define NJT  (QK / BN)            // 96 j-tiles
#define NT   (DIM / BK)           // 16 mainloop iters
#define NSTG 4

#define A_ST (BM * BK * 2)        // 8192 bytes/stage
#define B_ST (BN * BK * 2)        // 16384 bytes/stage
#define SMEM_EXT   2048
#define SMEM_BYTES (NSTG * (A_ST + B_ST) + SMEM_EXT)   // ~100KB

#define NSLOT (4 * NJT)           // 4 warp-columns x 96 j-tiles

// ---------------- static device scratch ----------------
__device__ __align__(16) __nv_bfloat16 g_xb[N_ROWS * DIM];
__device__ __align__(16) __nv_bfloat16 g_qb[QK * DIM];
__device__ float g_pt[NSLOT * N_ROWS];
__device__ float g_pm[NSLOT * N_ROWS];
__device__ int   g_hist[NCLS];
__device__ int   g_meta[4];   // [0]=targets is64, [1]=q_targets is64, [2]=order

__device__ __forceinline__ int load_tgt(const void* p, int i, int is64) {
    if (is64) return (int)((const long long*)p)[i];
    return ((const int*)p)[i];
}

// ---------------- helpers ----------------
__device__ __forceinline__ uint32_t smem_u32(const void* p) {
    uint32_t a;
    asm("{ .reg .u64 t; cvta.to.shared.u64 t, %1; cvt.u32.u64 %0, t; }" : "=r"(a) : "l"(p));
    return a;
}
__device__ __forceinline__ uint32_t swz(uint32_t o) { return o ^ ((o >> 3) & 0x70u); }

__device__ __forceinline__ void cpasync16(uint32_t s, const void* g) {
    asm volatile("cp.async.cg.shared.global [%0], [%1], 16;" :: "r"(s), "l"(g) : "memory");
}
__device__ __forceinline__ void cp_commit() {
    asm volatile("cp.async.commit_group;" ::: "memory");
}
__device__ __forceinline__ void ldm4(uint32_t a, uint32_t& r0, uint32_t& r1,
                                     uint32_t& r2, uint32_t& r3) {
    asm volatile("ldmatrix.sync.aligned.m8n8.x4.shared.b16 {%0,%1,%2,%3}, [%4];"
                 : "=r"(r0), "=r"(r1), "=r"(r2), "=r"(r3) : "r"(a));
}
__device__ __forceinline__ void mma16816(float* c, const uint32_t* a, const uint32_t* b) {
    asm volatile(
        "mma.sync.aligned.m16n8k16.row.col.f32.bf16.bf16.f32 "
        "{%0,%1,%2,%3}, {%4,%5,%6,%7}, {%8,%9}, {%0,%1,%2,%3};"
        : "+f"(c[0]), "+f"(c[1]), "+f"(c[2]), "+f"(c[3])
        : "r"(a[0]), "r"(a[1]), "r"(a[2]), "r"(a[3]), "r"(b[0]), "r"(b[1]));
}

// ---------------- k_init ----------------
__global__ void k_init(const void* targets, const void* q_targets, const void* order_p) {
    int t = threadIdx.x;  // 32 threads
    unsigned v = ((const unsigned*)targets)[2 * t + 1];
    unsigned any = __ballot_sync(0xffffffffu, v != 0u);
    if (t == 0) g_meta[0] = (any == 0u) ? 1 : 0;
    unsigned w = ((const unsigned*)q_targets)[2 * t + 1];
    unsigned anyq = __ballot_sync(0xffffffffu, w != 0u);
    if (t == 0) g_meta[1] = (anyq == 0u) ? 1 : 0;
    if (t == 0) g_meta[2] = ((const int*)order_p)[0];
    if (t < NCLS) g_hist[t] = 0;
}

// ---------------- k_convert: L2-norm + bf16 cast ----------------
__global__ void k_convert(const float* __restrict__ x, const float* __restrict__ q) {
    int warp = (blockIdx.x * blockDim.x + threadIdx.x) >> 5;
    int lane = threadIdx.x & 31;
    if (warp >= N_ROWS + QK) return;
    const float* src;
    __nv_bfloat16* dst;
    if (warp < N_ROWS) { src = x + (size_t)warp * DIM; dst = g_xb + (size_t)warp * DIM; }
    else { src = q + (size_t)(warp - N_ROWS) * DIM; dst = g_qb + (size_t)(warp - N_ROWS) * DIM; }
    const float2* s2 = (const float2*)src;
    float2 v[8];
    float s = 0.f;
    #pragma unroll
    for (int c = 0; c < 8; c++) {
        v[c] = s2[lane + c * 32];
        s += v[c].x * v[c].x + v[c].y * v[c].y;
    }
    #pragma unroll
    for (int o = 16; o > 0; o >>= 1) s += __shfl_xor_sync(0xffffffffu, s, o);
    float inv = 1.f / fmaxf(sqrtf(s), 1e-12f);
    __nv_bfloat162* d2 = (__nv_bfloat162*)dst;
    #pragma unroll
    for (int c = 0; c < 8; c++) {
        __nv_bfloat162 b;
        b.x = __float2bfloat16_rn(v[c].x * inv);
        b.y = __float2bfloat16_rn(v[c].y * inv);
        d2[lane + c * 32] = b;
    }
}

// ---------------- k_hist ----------------
__global__ void k_hist(const void* q_targets) {
    int i = blockIdx.x * blockDim.x + threadIdx.x;
    if (i >= KQ) return;
    int v = load_tgt(q_targets, g_meta[2] * KQ + i, g_meta[1]);
    atomicAdd(&g_hist[v], 1);
}

// ---------------- k_main: HMMA bf16 GEMM + fused exp epilogue ----------------
__global__ void __launch_bounds__(256, 1)
k_main(const void* __restrict__ targets, const void* __restrict__ q_targets) {
    extern __shared__ char smem_raw[];
    const uint32_t smem = smem_u32(smem_raw);
    const uint32_t aBase = smem;
    const uint32_t bBase = smem + NSTG * A_ST;
    int* qtp = (int*)(smem_raw + NSTG * (A_ST + B_ST));

    const int tid  = threadIdx.x;
    const int wid  = tid >> 5;
    const int lane = tid & 31;
    const int wm   = wid & 1;          // 2 warp-rows (64 M each)
    const int wn   = wid >> 1;         // 4 warp-cols (64 N each)
    const int i0   = blockIdx.y * BM;
    const int j0   = blockIdx.x * BN;

    const int is64t = g_meta[0];
    const int is64q = g_meta[1];
    const bool otile = (j0 / KQ) == g_meta[2];

    if (otile) qtp[tid] = load_tgt(q_targets, j0 + tid, is64q);

    // per-thread cp.async source/dest precompute
    // A: 2 chunks of 16B; B: 4 chunks of 16B
    uint32_t dstA[2], dstB[4];
    const char* srcA[2];
    const char* srcB[4];
    #pragma unroll
    for (int l = 0; l < 2; l++) {
        int idx = tid + l * 256, row = idx >> 2, c = idx & 3;
        dstA[l] = swz((uint32_t)(row * 64 + c * 16));
        srcA[l] = (const char*)(g_xb + ((size_t)(i0 + row) * DIM + c * 8));
    }
    #pragma unroll
    for (int l = 0; l < 4; l++) {
        int idx = tid + l * 256, row = idx >> 2, c = idx & 3;
        dstB[l] = swz((uint32_t)(row * 64 + c * 16));
        srcB[l] = (const char*)(g_qb + ((size_t)(j0 + row) * DIM + c * 8));
    }

    // ldmatrix per-lane offsets (within a stage), ks=0; ks=1 -> XOR 32
    uint32_t offA0[4], offB0[4];
    {
        int kc = lane >> 4;                 // 0/1 -> k0/k8 halves for A
        #pragma unroll
        for (int m = 0; m < 4; m++) {
            int rowA = wm * 64 + m * 16 + (lane & 15);
            offA0[m] = swz((uint32_t)(rowA * 64 + kc * 16));
        }
        int kc2 = (lane >> 3) & 1;
        #pragma unroll
        for (int p = 0; p < 4; p++) {
            int rowB = wn * 64 + p * 16 + (lane & 7) + ((lane >> 4) & 1) * 8;
            offB0[p] = swz((uint32_t)(rowB * 64 + kc2 * 16));
        }
    }

    float c[4][8][4];
    #pragma unroll
    for (int m = 0; m < 4; m++)
        #pragma unroll
        for (int n = 0; n < 8; n++)
            #pragma unroll
            for (int e = 0; e < 4; e++) c[m][n][e] = 0.f;

    // ---- prologue: stages 0,1,2 ----
    #pragma unroll
    for (int s = 0; s < 3; s++) {
        #pragma unroll
        for (int l = 0; l < 2; l++) { cpasync16(aBase + s * A_ST + dstA[l], srcA[l]); srcA[l] += 64; }
        #pragma unroll
        for (int l = 0; l < 4; l++) { cpasync16(bBase + s * B_ST + dstB[l], srcB[l]); srcB[l] += 64; }
        cp_commit();
    }

    for (int kt = 0; kt < NT; kt++) {
        if (kt < NT - 2)      asm volatile("cp.async.wait_group 2;" ::: "memory");
        else if (kt == NT - 2) asm volatile("cp.async.wait_group 1;" ::: "memory");
        else                   asm volatile("cp.async.wait_group 0;" ::: "memory");
        __syncthreads();

        if (kt + 3 < NT) {
            int s = (kt + 3) & (NSTG - 1);
            #pragma unroll
            for (int l = 0; l < 2; l++) { cpasync16(aBase + s * A_ST + dstA[l], srcA[l]); srcA[l] += 64; }
            #pragma unroll
            for (int l = 0; l < 4; l++) { cpasync16(bBase + s * B_ST + dstB[l], srcB[l]); srcB[l] += 64; }
            cp_commit();
        }

        const uint32_t aS = aBase + (kt & (NSTG - 1)) * A_ST;
        const uint32_t bS = bBase + (kt & (NSTG - 1)) * B_ST;
        #pragma unroll
        for (int ks = 0; ks < 2; ks++) {
            const uint32_t kx = ks * 32;
            uint32_t a[4][4], b[8][2];
            #pragma unroll
            for (int m = 0; m < 4; m++)
                ldm4(aS + (offA0[m] ^ kx), a[m][0], a[m][1], a[m][2], a[m][3]);
            #pragma unroll
            for (int p = 0; p < 4; p++)
                ldm4(bS + (offB0[p] ^ kx), b[2*p][0], b[2*p][1], b[2*p+1][0], b[2*p+1][1]);
            #pragma unroll
            for (int m = 0; m < 4; m++)
                #pragma unroll
                for (int n = 0; n < 8; n++)
                    mma16816(c[m][n], a[m], b[n]);
        }
    }

    // ---- epilogue: exp + per-row (total, masked) partial sums ----
    const int l4  = lane >> 2;
    const int lm4 = lane & 3;
    int qtv[16];
    if (otile) {
        #pragma unroll
        for (int n = 0; n < 8; n++)
            #pragma unroll
            for (int e = 0; e < 2; e++)
                qtv[n * 2 + e] = qtp[wn * 64 + n * 8 + lm4 * 2 + e];
    }
    #pragma unroll
    for (int m = 0; m < 4; m++) {
        #pragma unroll
        for (int half = 0; half < 2; half++) {
            const int i = i0 + wm * 64 + m * 16 + half * 8 + l4;
            const int tg = load_tgt(targets, i, is64t);
            float s = 0.f, mk = 0.f;
            #pragma unroll
            for (int n = 0; n < 8; n++) {
                #pragma unroll
                for (int e = 0; e < 2; e++) {
                    float ex = __expf(fmaf(4.f, c[m][n][half * 2 + e], -4.f));
                    s += ex;
                    if (otile && qtv[n * 2 + e] == tg) mk += ex;
                }
            }
            s  += __shfl_xor_sync(0xffffffffu, s, 1);
            s  += __shfl_xor_sync(0xffffffffu, s, 2);
            mk += __shfl_xor_sync(0xffffffffu, mk, 1);
            mk += __shfl_xor_sync(0xffffffffu, mk, 2);
            if (lm4 == 0) {
                int slot = (wn * NJT + blockIdx.x) * N_ROWS + i;
                g_pt[slot] = s;
                g_pm[slot] = mk;
            }
        }
    }
}

// ---------------- k_final ----------------
__global__ void k_final(float* __restrict__ out, const void* __restrict__ targets) {
    __shared__ float red[1024];
    int tid = threadIdx.x;  // 1024
    float local = 0.f;
    for (int i = tid; i < N_ROWS; i += 1024) {
        float tot = 0.f, msk = 0.f;
        for (int t = 0; t < NSLOT; t++) {
            tot += g_pt[t * N_ROWS + i];
            msk += g_pm[t * N_ROWS + i];
        }
        int tg = load_tgt(targets, i, g_meta[0]);
        float cnt = (float)(QK - g_hist[tg]);
        local += logf((tot - msk) / cnt);
    }
    red[tid] = local;
    __syncthreads();
    for (int s = 512; s > 0; s >>= 1) {
        if (tid < s) red[tid] += red[tid + s];
        __syncthreads();
    }
    if (tid == 0) out[0] = red[0] / (float)N_ROWS;
}

// ---------------- launch ----------------
extern "C" void kernel_launch(void* const* d_in, const int* in_sizes, int n_in,
                              void* d_out, int out_size) {
    const float* x       = (const float*)d_in[0];
    const float* q       = (const float*)d_in[1];
    const void*  targets = d_in[2];
    const void*  q_tgts  = d_in[3];
    const void*  order_p = d_in[4];

    cudaFuncSetAttribute(k_main, cudaFuncAttributeMaxDynamicSharedMemorySize, SMEM_BYTES);

    k_init<<<1, 32>>>(targets, q_tgts, order_p);
    {
        int total_warps = N_ROWS + QK;              // 26624
        int blocks = (total_warps + 7) / 8;
        k_convert<<<blocks, 256>>>(x, q);
    }
    k_hist<<<(KQ + 255) / 256, 256>>>(q_tgts);
    dim3 grid(NJT, N_ROWS / BM);                    // 96 x 16
    k_main<<<grid, 256, SMEM_BYTES>>>(targets, q_tgts);
    k_final<<<1, 1024>>>((float*)d_out, targets);
}

// round 8
// speedup vs baseline: 6.8964x; 1.3141x over previous
#include <cuda_runtime.h>
#include <cuda_bf16.h>
#include <math.h>
#include <stdint.h>

// ---------------- problem shapes ----------------
#define N_ROWS   2048
#define DIM      512
#define NQ       3
#define KQ       8192
#define QK       (NQ * KQ)        // 24576
#define NCLS     16

// ---------------- GEMM tiling -------------------
#define BM   128                  // x rows per CTA
#define BN   256                  // q rows per CTA
#define BK   64                   // bf16 K per stage (128B rows = SW128 atom)
#define NJT  (QK / BN)            // 96 j-tiles
#define NT   (DIM / BK)           // 8 mainloop iters
#define NSTG 3

#define A_ST (BM * BK * 2)        // 16384 bytes/stage
#define B_ST (BN * BK * 2)        // 32768 bytes/stage
#define QTP_OFF  (NSTG * (A_ST + B_ST))         // 147456
#define RED_OFF  (QTP_OFF + 1024)
#define RED_PITCH 9
#define SMEM_BYTES (RED_OFF + 2 * BM * RED_PITCH * 4)   // ~157KB

// ---------------- static device scratch ----------------
__device__ __align__(16) __nv_bfloat16 g_xb[N_ROWS * DIM];
__device__ __align__(16) __nv_bfloat16 g_qb[QK * DIM];
__device__ float g_pt[NJT * N_ROWS];
__device__ float g_pm[NJT * N_ROWS];
__device__ float g_row[N_ROWS];
__device__ int   g_hist[NCLS];
__device__ int   g_meta[4];   // [0]=targets is64, [1]=q_targets is64, [2]=order

__device__ __forceinline__ int load_tgt(const void* p, int i, int is64) {
    if (is64) return (int)((const long long*)p)[i];
    return ((const int*)p)[i];
}

// ---------------- helpers ----------------
__device__ __forceinline__ uint32_t smem_u32(const void* p) {
    uint32_t a;
    asm("{ .reg .u64 t; cvta.to.shared.u64 t, %1; cvt.u32.u64 %0, t; }" : "=r"(a) : "l"(p));
    return a;
}
__device__ __forceinline__ uint32_t swz(uint32_t o) { return o ^ ((o >> 3) & 0x70u); }

__device__ __forceinline__ void cpasync16(uint32_t s, const void* g) {
    asm volatile("cp.async.cg.shared.global [%0], [%1], 16;" :: "r"(s), "l"(g) : "memory");
}
__device__ __forceinline__ void cp_commit() {
    asm volatile("cp.async.commit_group;" ::: "memory");
}
__device__ __forceinline__ void ldm4(uint32_t a, uint32_t& r0, uint32_t& r1,
                                     uint32_t& r2, uint32_t& r3) {
    asm volatile("ldmatrix.sync.aligned.m8n8.x4.shared.b16 {%0,%1,%2,%3}, [%4];"
                 : "=r"(r0), "=r"(r1), "=r"(r2), "=r"(r3) : "r"(a));
}
__device__ __forceinline__ void mma16816(float* c, const uint32_t* a, const uint32_t* b) {
    asm volatile(
        "mma.sync.aligned.m16n8k16.row.col.f32.bf16.bf16.f32 "
        "{%0,%1,%2,%3}, {%4,%5,%6,%7}, {%8,%9}, {%0,%1,%2,%3};"
        : "+f"(c[0]), "+f"(c[1]), "+f"(c[2]), "+f"(c[3])
        : "r"(a[0]), "r"(a[1]), "r"(a[2]), "r"(a[3]), "r"(b[0]), "r"(b[1]));
}

// ---------------- k_init ----------------
__global__ void k_init(const void* targets, const void* q_targets, const void* order_p) {
    int t = threadIdx.x;  // 32 threads
    unsigned v = ((const unsigned*)targets)[2 * t + 1];
    unsigned any = __ballot_sync(0xffffffffu, v != 0u);
    if (t == 0) g_meta[0] = (any == 0u) ? 1 : 0;
    unsigned w = ((const unsigned*)q_targets)[2 * t + 1];
    unsigned anyq = __ballot_sync(0xffffffffu, w != 0u);
    if (t == 0) g_meta[1] = (anyq == 0u) ? 1 : 0;
    if (t == 0) g_meta[2] = ((const int*)order_p)[0];
    if (t < NCLS) g_hist[t] = 0;
}

// ---------------- k_convert: L2-norm + bf16 cast ----------------
__global__ void k_convert(const float* __restrict__ x, const float* __restrict__ q) {
    int warp = (blockIdx.x * blockDim.x + threadIdx.x) >> 5;
    int lane = threadIdx.x & 31;
    if (warp >= N_ROWS + QK) return;
    const float* src;
    __nv_bfloat16* dst;
    if (warp < N_ROWS) { src = x + (size_t)warp * DIM; dst = g_xb + (size_t)warp * DIM; }
    else { src = q + (size_t)(warp - N_ROWS) * DIM; dst = g_qb + (size_t)(warp - N_ROWS) * DIM; }
    const float2* s2 = (const float2*)src;
    float2 v[8];
    float s = 0.f;
    #pragma unroll
    for (int c = 0; c < 8; c++) {
        v[c] = s2[lane + c * 32];
        s += v[c].x * v[c].x + v[c].y * v[c].y;
    }
    #pragma unroll
    for (int o = 16; o > 0; o >>= 1) s += __shfl_xor_sync(0xffffffffu, s, o);
    float inv = 1.f / fmaxf(sqrtf(s), 1e-12f);
    __nv_bfloat162* d2 = (__nv_bfloat162*)dst;
    #pragma unroll
    for (int c = 0; c < 8; c++) {
        __nv_bfloat162 b;
        b.x = __float2bfloat16_rn(v[c].x * inv);
        b.y = __float2bfloat16_rn(v[c].y * inv);
        d2[lane + c * 32] = b;
    }
}

// ---------------- k_hist ----------------
__global__ void k_hist(const void* q_targets) {
    int i = blockIdx.x * blockDim.x + threadIdx.x;
    if (i >= KQ) return;
    int v = load_tgt(q_targets, g_meta[2] * KQ + i, g_meta[1]);
    atomicAdd(&g_hist[v], 1);
}

// ---------------- k_main: HMMA bf16 GEMM + fused exp epilogue ----------------
__global__ void __launch_bounds__(512, 1)
k_main(const void* __restrict__ targets, const void* __restrict__ q_targets) {
    extern __shared__ char smem_raw[];
    const uint32_t smem = smem_u32(smem_raw);
    const uint32_t aBase = smem;
    const uint32_t bBase = smem + NSTG * A_ST;
    int*   qtp  = (int*)(smem_raw + QTP_OFF);
    float* sm_s = (float*)(smem_raw + RED_OFF);
    float* sm_m = sm_s + BM * RED_PITCH;

    const int tid  = threadIdx.x;
    const int wid  = tid >> 5;
    const int lane = tid & 31;
    const int wm   = wid & 1;          // 2 warp-rows (64 M each)
    const int wn   = wid >> 1;         // 8 warp-cols (32 N each)
    const int i0   = blockIdx.y * BM;
    const int j0   = blockIdx.x * BN;

    const int is64t = g_meta[0];
    const int is64q = g_meta[1];
    const bool otile = (j0 / KQ) == g_meta[2];

    if (otile && tid < BN) qtp[tid] = load_tgt(q_targets, j0 + tid, is64q);

    // per-thread cp.async dest/src: A 2 chunks of 16B, B 4 chunks of 16B
    uint32_t dstA[2], dstB[4];
    const char* srcA[2];
    const char* srcB[4];
    #pragma unroll
    for (int l = 0; l < 2; l++) {
        int idx = tid + l * 512, row = idx >> 3, c = idx & 7;
        dstA[l] = swz((uint32_t)(row * 128 + c * 16));
        srcA[l] = (const char*)(g_xb + ((size_t)(i0 + row) * DIM + c * 8));
    }
    #pragma unroll
    for (int l = 0; l < 4; l++) {
        int idx = tid + l * 512, row = idx >> 3, c = idx & 7;
        dstB[l] = swz((uint32_t)(row * 128 + c * 16));
        srcB[l] = (const char*)(g_qb + ((size_t)(j0 + row) * DIM + c * 8));
    }

    // ldmatrix per-lane byte offsets within a stage (ks -> XOR ks*32)
    uint32_t offA0[4], offB0[2];
    {
        int kc = lane >> 4;                 // 16B half
        #pragma unroll
        for (int m = 0; m < 4; m++) {
            int rowA = wm * 64 + m * 16 + (lane & 15);
            offA0[m] = swz((uint32_t)(rowA * 128 + kc * 16));
        }
        int kc2 = (lane >> 3) & 1;
        #pragma unroll
        for (int p = 0; p < 2; p++) {
            int rowB = wn * 32 + p * 16 + (lane & 7) + ((lane >> 4) & 1) * 8;
            offB0[p] = swz((uint32_t)(rowB * 128 + kc2 * 16));
        }
    }

    float c[4][4][4];
    #pragma unroll
    for (int m = 0; m < 4; m++)
        #pragma unroll
        for (int n = 0; n < 4; n++)
            #pragma unroll
            for (int e = 0; e < 4; e++) c[m][n][e] = 0.f;

    // ---- prologue: stages 0,1 ----
    #pragma unroll
    for (int s = 0; s < 2; s++) {
        #pragma unroll
        for (int l = 0; l < 2; l++) { cpasync16(aBase + s * A_ST + dstA[l], srcA[l]); srcA[l] += 128; }
        #pragma unroll
        for (int l = 0; l < 4; l++) { cpasync16(bBase + s * B_ST + dstB[l], srcB[l]); srcB[l] += 128; }
        cp_commit();
    }

    for (int kt = 0; kt < NT; kt++) {
        if (kt < NT - 1) asm volatile("cp.async.wait_group 1;" ::: "memory");
        else             asm volatile("cp.async.wait_group 0;" ::: "memory");
        __syncthreads();

        if (kt + 2 < NT) {
            int s = (kt + 2) % NSTG;
            #pragma unroll
            for (int l = 0; l < 2; l++) { cpasync16(aBase + s * A_ST + dstA[l], srcA[l]); srcA[l] += 128; }
            #pragma unroll
            for (int l = 0; l < 4; l++) { cpasync16(bBase + s * B_ST + dstB[l], srcB[l]); srcB[l] += 128; }
            cp_commit();
        }

        const uint32_t aS = aBase + (kt % NSTG) * A_ST;
        const uint32_t bS = bBase + (kt % NSTG) * B_ST;
        #pragma unroll
        for (int ks = 0; ks < 4; ks++) {
            const uint32_t kx = ks * 32;
            uint32_t a[4][4], b[4][2];
            #pragma unroll
            for (int m = 0; m < 4; m++)
                ldm4(aS + (offA0[m] ^ kx), a[m][0], a[m][1], a[m][2], a[m][3]);
            #pragma unroll
            for (int p = 0; p < 2; p++)
                ldm4(bS + (offB0[p] ^ kx), b[2*p][0], b[2*p][1], b[2*p+1][0], b[2*p+1][1]);
            #pragma unroll
            for (int m = 0; m < 4; m++)
                #pragma unroll
                for (int n = 0; n < 4; n++)
                    mma16816(c[m][n], a[m], b[n]);
        }
    }

    // ---- epilogue: exp + per-row (total, masked) partial sums ----
    const int l4  = lane >> 2;
    const int lm4 = lane & 3;
    int qtv[8];
    if (otile) {
        #pragma unroll
        for (int n = 0; n < 4; n++)
            #pragma unroll
            for (int e = 0; e < 2; e++)
                qtv[n * 2 + e] = qtp[wn * 32 + n * 8 + lm4 * 2 + e];
    }
    #pragma unroll
    for (int m = 0; m < 4; m++) {
        #pragma unroll
        for (int half = 0; half < 2; half++) {
            const int rl = wm * 64 + m * 16 + half * 8 + l4;   // local row
            const int i  = i0 + rl;
            const int tg = load_tgt(targets, i, is64t);
            float s = 0.f, mk = 0.f;
            #pragma unroll
            for (int n = 0; n < 4; n++) {
                #pragma unroll
                for (int e = 0; e < 2; e++) {
                    float ex = __expf(fmaf(4.f, c[m][n][half * 2 + e], -4.f));
                    s += ex;
                    if (otile && qtv[n * 2 + e] == tg) mk += ex;
                }
            }
            s  += __shfl_xor_sync(0xffffffffu, s, 1);
            s  += __shfl_xor_sync(0xffffffffu, s, 2);
            mk += __shfl_xor_sync(0xffffffffu, mk, 1);
            mk += __shfl_xor_sync(0xffffffffu, mk, 2);
            if (lm4 == 0) {
                sm_s[rl * RED_PITCH + wn] = s;
                sm_m[rl * RED_PITCH + wn] = mk;
            }
        }
    }
    __syncthreads();
    if (tid < BM) {
        float tot = 0.f, msk = 0.f;
        #pragma unroll
        for (int w = 0; w < 8; w++) {
            tot += sm_s[tid * RED_PITCH + w];
            msk += sm_m[tid * RED_PITCH + w];
        }
        g_pt[blockIdx.x * N_ROWS + i0 + tid] = tot;
        g_pm[blockIdx.x * N_ROWS + i0 + tid] = msk;
    }
}

// ---------------- k_rows: per-row log terms (parallel) ----------------
__global__ void k_rows(const void* __restrict__ targets) {
    int i = blockIdx.x * blockDim.x + threadIdx.x;   // 8 x 256 = 2048
    float tot = 0.f, msk = 0.f;
    for (int t = 0; t < NJT; t++) {
        tot += g_pt[t * N_ROWS + i];
        msk += g_pm[t * N_ROWS + i];
    }
    int tg = load_tgt(targets, i, g_meta[0]);
    float cnt = (float)(QK - g_hist[tg]);
    g_row[i] = logf((tot - msk) / cnt);
}

// ---------------- k_final: deterministic sum of 2048 row terms ----------------
__global__ void k_final(float* __restrict__ out) {
    __shared__ float red[1024];
    int tid = threadIdx.x;  // 1024
    red[tid] = g_row[tid] + g_row[tid + 1024];
    __syncthreads();
    for (int s = 512; s > 0; s >>= 1) {
        if (tid < s) red[tid] += red[tid + s];
        __syncthreads();
    }
    if (tid == 0) out[0] = red[0] / (float)N_ROWS;
}

// ---------------- launch ----------------
extern "C" void kernel_launch(void* const* d_in, const int* in_sizes, int n_in,
                              void* d_out, int out_size) {
    const float* x       = (const float*)d_in[0];
    const float* q       = (const float*)d_in[1];
    const void*  targets = d_in[2];
    const void*  q_tgts  = d_in[3];
    const void*  order_p = d_in[4];

    cudaFuncSetAttribute(k_main, cudaFuncAttributeMaxDynamicSharedMemorySize, SMEM_BYTES);

    k_init<<<1, 32>>>(targets, q_tgts, order_p);
    {
        int total_warps = N_ROWS + QK;              // 26624
        int blocks = (total_warps + 7) / 8;
        k_convert<<<blocks, 256>>>(x, q);
    }
    k_hist<<<(KQ + 255) / 256, 256>>>(q_tgts);
    dim3 grid(NJT, N_ROWS / BM);                    // 96 x 16
    k_main<<<grid, 512, SMEM_BYTES>>>(targets, q_tgts);
    k_rows<<<N_ROWS / 256, 256>>>(targets);
    k_final<<<1, 1024>>>((float*)d_out);
}

// round 9
// speedup vs baseline: 7.5693x; 1.0976x over previous
#include <cuda_runtime.h>
#include <cuda_bf16.h>
#include <math.h>
#include <stdint.h>

// ---------------- problem shapes ----------------
#define N_ROWS   2048
#define DIM      512
#define NQ       3
#define KQ       8192
#define QK       (NQ * KQ)        // 24576
#define NCLS     16

// ---------------- GEMM tiling -------------------
#define BM   128                  // x rows per CTA
#define BN   128                  // q rows per CTA
#define BK   64                   // bf16 K per stage (128B rows = SW128 atom)
#define NJT  (QK / BN)            // 192 j-tiles
#define NT   (DIM / BK)           // 8 mainloop iters
#define NSTG 3

#define A_ST (BM * BK * 2)        // 16384 bytes/stage
#define B_ST (BN * BK * 2)        // 16384 bytes/stage
#define QTP_OFF  (NSTG * (A_ST + B_ST))         // 98304
#define RED_OFF  (QTP_OFF + 512)
#define RED_PITCH 5
#define SMEM_BYTES (RED_OFF + 2 * BM * RED_PITCH * 4)   // ~104KB

// ---------------- static device scratch ----------------
__device__ __align__(16) __nv_bfloat16 g_xb[N_ROWS * DIM];
__device__ __align__(16) __nv_bfloat16 g_qb[QK * DIM];
__device__ float g_pt[NJT * N_ROWS];
__device__ float g_pm[NJT * N_ROWS];
__device__ float g_row[N_ROWS];
__device__ int   g_hist[NCLS];
__device__ int   g_meta[4];   // [0]=targets is64, [1]=q_targets is64, [2]=order

__device__ __forceinline__ int load_tgt(const void* p, int i, int is64) {
    if (is64) return (int)((const long long*)p)[i];
    return ((const int*)p)[i];
}

// ---------------- helpers ----------------
__device__ __forceinline__ uint32_t smem_u32(const void* p) {
    uint32_t a;
    asm("{ .reg .u64 t; cvta.to.shared.u64 t, %1; cvt.u32.u64 %0, t; }" : "=r"(a) : "l"(p));
    return a;
}
__device__ __forceinline__ uint32_t swz(uint32_t o) { return o ^ ((o >> 3) & 0x70u); }

__device__ __forceinline__ void cpasync16(uint32_t s, const void* g) {
    asm volatile("cp.async.cg.shared.global [%0], [%1], 16;" :: "r"(s), "l"(g) : "memory");
}
__device__ __forceinline__ void cp_commit() {
    asm volatile("cp.async.commit_group;" ::: "memory");
}
__device__ __forceinline__ void ldm4(uint32_t a, uint32_t& r0, uint32_t& r1,
                                     uint32_t& r2, uint32_t& r3) {
    asm volatile("ldmatrix.sync.aligned.m8n8.x4.shared.b16 {%0,%1,%2,%3}, [%4];"
                 : "=r"(r0), "=r"(r1), "=r"(r2), "=r"(r3) : "r"(a));
}
__device__ __forceinline__ void mma16816(float* c, const uint32_t* a, const uint32_t* b) {
    asm volatile(
        "mma.sync.aligned.m16n8k16.row.col.f32.bf16.bf16.f32 "
        "{%0,%1,%2,%3}, {%4,%5,%6,%7}, {%8,%9}, {%0,%1,%2,%3};"
        : "+f"(c[0]), "+f"(c[1]), "+f"(c[2]), "+f"(c[3])
        : "r"(a[0]), "r"(a[1]), "r"(a[2]), "r"(a[3]), "r"(b[0]), "r"(b[1]));
}

// ---------------- k_init ----------------
__global__ void k_init(const void* targets, const void* q_targets, const void* order_p) {
    int t = threadIdx.x;  // 32 threads
    unsigned v = ((const unsigned*)targets)[2 * t + 1];
    unsigned any = __ballot_sync(0xffffffffu, v != 0u);
    if (t == 0) g_meta[0] = (any == 0u) ? 1 : 0;
    unsigned w = ((const unsigned*)q_targets)[2 * t + 1];
    unsigned anyq = __ballot_sync(0xffffffffu, w != 0u);
    if (t == 0) g_meta[1] = (anyq == 0u) ? 1 : 0;
    if (t == 0) g_meta[2] = ((const int*)order_p)[0];
    if (t < NCLS) g_hist[t] = 0;
}

// ---------------- k_convert: L2-norm + bf16 cast ----------------
__global__ void k_convert(const float* __restrict__ x, const float* __restrict__ q) {
    int warp = (blockIdx.x * blockDim.x + threadIdx.x) >> 5;
    int lane = threadIdx.x & 31;
    if (warp >= N_ROWS + QK) return;
    const float* src;
    __nv_bfloat16* dst;
    if (warp < N_ROWS) { src = x + (size_t)warp * DIM; dst = g_xb + (size_t)warp * DIM; }
    else { src = q + (size_t)(warp - N_ROWS) * DIM; dst = g_qb + (size_t)(warp - N_ROWS) * DIM; }
    const float2* s2 = (const float2*)src;
    float2 v[8];
    float s = 0.f;
    #pragma unroll
    for (int c = 0; c < 8; c++) {
        v[c] = s2[lane + c * 32];
        s += v[c].x * v[c].x + v[c].y * v[c].y;
    }
    #pragma unroll
    for (int o = 16; o > 0; o >>= 1) s += __shfl_xor_sync(0xffffffffu, s, o);
    float inv = 1.f / fmaxf(sqrtf(s), 1e-12f);
    __nv_bfloat162* d2 = (__nv_bfloat162*)dst;
    #pragma unroll
    for (int c = 0; c < 8; c++) {
        __nv_bfloat162 b;
        b.x = __float2bfloat16_rn(v[c].x * inv);
        b.y = __float2bfloat16_rn(v[c].y * inv);
        d2[lane + c * 32] = b;
    }
}

// ---------------- k_hist ----------------
__global__ void k_hist(const void* q_targets) {
    int i = blockIdx.x * blockDim.x + threadIdx.x;
    if (i >= KQ) return;
    int v = load_tgt(q_targets, g_meta[2] * KQ + i, g_meta[1]);
    atomicAdd(&g_hist[v], 1);
}

// ---------------- k_main: HMMA bf16 GEMM + fused exp epilogue ----------------
__global__ void __launch_bounds__(256, 2)
k_main(const void* __restrict__ targets, const void* __restrict__ q_targets) {
    extern __shared__ char smem_raw[];
    const uint32_t smem = smem_u32(smem_raw);
    const uint32_t aBase = smem;
    const uint32_t bBase = smem + NSTG * A_ST;
    int*   qtp  = (int*)(smem_raw + QTP_OFF);
    float* sm_s = (float*)(smem_raw + RED_OFF);
    float* sm_m = sm_s + BM * RED_PITCH;

    const int tid  = threadIdx.x;
    const int wid  = tid >> 5;
    const int lane = tid & 31;
    const int wm   = wid & 1;          // 2 warp-rows (64 M each)
    const int wn   = wid >> 1;         // 4 warp-cols (32 N each)
    const int i0   = blockIdx.y * BM;
    const int j0   = blockIdx.x * BN;

    const int is64t = g_meta[0];
    const int is64q = g_meta[1];
    const bool otile = (j0 / KQ) == g_meta[2];

    if (otile && tid < BN) qtp[tid] = load_tgt(q_targets, j0 + tid, is64q);

    // per-thread cp.async dest/src: A and B each 4 chunks of 16B per stage
    uint32_t dstA[4], dstB[4];
    const char* srcA[4];
    const char* srcB[4];
    #pragma unroll
    for (int l = 0; l < 4; l++) {
        int idx = tid + l * 256, row = idx >> 3, c = idx & 7;
        dstA[l] = swz((uint32_t)(row * 128 + c * 16));
        srcA[l] = (const char*)(g_xb + ((size_t)(i0 + row) * DIM + c * 8));
        dstB[l] = dstA[l];
        srcB[l] = (const char*)(g_qb + ((size_t)(j0 + row) * DIM + c * 8));
    }

    // ldmatrix per-lane byte offsets within a stage (ks -> XOR ks*32)
    uint32_t offA0[4], offB0[2];
    {
        int kc = lane >> 4;                 // 16B half
        #pragma unroll
        for (int m = 0; m < 4; m++) {
            int rowA = wm * 64 + m * 16 + (lane & 15);
            offA0[m] = swz((uint32_t)(rowA * 128 + kc * 16));
        }
        int kc2 = (lane >> 3) & 1;
        #pragma unroll
        for (int p = 0; p < 2; p++) {
            int rowB = wn * 32 + p * 16 + (lane & 7) + ((lane >> 4) & 1) * 8;
            offB0[p] = swz((uint32_t)(rowB * 128 + kc2 * 16));
        }
    }

    float c[4][4][4];
    #pragma unroll
    for (int m = 0; m < 4; m++)
        #pragma unroll
        for (int n = 0; n < 4; n++)
            #pragma unroll
            for (int e = 0; e < 4; e++) c[m][n][e] = 0.f;

    // register-double-buffered fragments
    uint32_t afr[2][4][4], bfr[2][4][2];

    // ---- prologue: stages 0,1 ----
    #pragma unroll
    for (int s = 0; s < 2; s++) {
        #pragma unroll
        for (int l = 0; l < 4; l++) { cpasync16(aBase + s * A_ST + dstA[l], srcA[l]); srcA[l] += 128; }
        #pragma unroll
        for (int l = 0; l < 4; l++) { cpasync16(bBase + s * B_ST + dstB[l], srcB[l]); srcB[l] += 128; }
        cp_commit();
    }

    for (int kt = 0; kt < NT; kt++) {
        if (kt < NT - 1) asm volatile("cp.async.wait_group 1;" ::: "memory");
        else             asm volatile("cp.async.wait_group 0;" ::: "memory");
        __syncthreads();

        if (kt + 2 < NT) {
            int s = (kt + 2) % NSTG;
            #pragma unroll
            for (int l = 0; l < 4; l++) { cpasync16(aBase + s * A_ST + dstA[l], srcA[l]); srcA[l] += 128; }
            #pragma unroll
            for (int l = 0; l < 4; l++) { cpasync16(bBase + s * B_ST + dstB[l], srcB[l]); srcB[l] += 128; }
            cp_commit();
        }

        const uint32_t aS = aBase + (kt % NSTG) * A_ST;
        const uint32_t bS = bBase + (kt % NSTG) * B_ST;

        // load ks=0 fragments into buffer 0
        #pragma unroll
        for (int m = 0; m < 4; m++)
            ldm4(aS + offA0[m], afr[0][m][0], afr[0][m][1], afr[0][m][2], afr[0][m][3]);
        #pragma unroll
        for (int p = 0; p < 2; p++)
            ldm4(bS + offB0[p], bfr[0][2*p][0], bfr[0][2*p][1], bfr[0][2*p+1][0], bfr[0][2*p+1][1]);

        #pragma unroll
        for (int ks = 0; ks < 4; ks++) {
            const int cur = ks & 1;
            if (ks < 3) {
                const int nxt = cur ^ 1;
                const uint32_t kx = (ks + 1) * 32;
                #pragma unroll
                for (int m = 0; m < 4; m++)
                    ldm4(aS + (offA0[m] ^ kx), afr[nxt][m][0], afr[nxt][m][1],
                         afr[nxt][m][2], afr[nxt][m][3]);
                #pragma unroll
                for (int p = 0; p < 2; p++)
                    ldm4(bS + (offB0[p] ^ kx), bfr[nxt][2*p][0], bfr[nxt][2*p][1],
                         bfr[nxt][2*p+1][0], bfr[nxt][2*p+1][1]);
            }
            #pragma unroll
            for (int m = 0; m < 4; m++)
                #pragma unroll
                for (int n = 0; n < 4; n++)
                    mma16816(c[m][n], afr[cur][m], bfr[cur][n]);
        }
    }

    // ---- epilogue: exp + per-row (total, masked) partial sums ----
    const int l4  = lane >> 2;
    const int lm4 = lane & 3;
    int qtv[8];
    if (otile) {
        #pragma unroll
        for (int n = 0; n < 4; n++)
            #pragma unroll
            for (int e = 0; e < 2; e++)
                qtv[n * 2 + e] = qtp[wn * 32 + n * 8 + lm4 * 2 + e];
    }
    #pragma unroll
    for (int m = 0; m < 4; m++) {
        #pragma unroll
        for (int half = 0; half < 2; half++) {
            const int rl = wm * 64 + m * 16 + half * 8 + l4;   // local row
            const int i  = i0 + rl;
            const int tg = load_tgt(targets, i, is64t);
            float s = 0.f, mk = 0.f;
            #pragma unroll
            for (int n = 0; n < 4; n++) {
                #pragma unroll
                for (int e = 0; e < 2; e++) {
                    float ex = __expf(fmaf(4.f, c[m][n][half * 2 + e], -4.f));
                    s += ex;
                    if (otile && qtv[n * 2 + e] == tg) mk += ex;
                }
            }
            s  += __shfl_xor_sync(0xffffffffu, s, 1);
            s  += __shfl_xor_sync(0xffffffffu, s, 2);
            mk += __shfl_xor_sync(0xffffffffu, mk, 1);
            mk += __shfl_xor_sync(0xffffffffu, mk, 2);
            if (lm4 == 0) {
                sm_s[rl * RED_PITCH + wn] = s;
                sm_m[rl * RED_PITCH + wn] = mk;
            }
        }
    }
    __syncthreads();
    if (tid < BM) {
        float tot = 0.f, msk = 0.f;
        #pragma unroll
        for (int w = 0; w < 4; w++) {
            tot += sm_s[tid * RED_PITCH + w];
            msk += sm_m[tid * RED_PITCH + w];
        }
        g_pt[blockIdx.x * N_ROWS + i0 + tid] = tot;
        g_pm[blockIdx.x * N_ROWS + i0 + tid] = msk;
    }
}

// ---------------- k_rows: per-row log terms (parallel) ----------------
__global__ void k_rows(const void* __restrict__ targets) {
    int i = blockIdx.x * blockDim.x + threadIdx.x;   // 8 x 256 = 2048
    float tot = 0.f, msk = 0.f;
    for (int t = 0; t < NJT; t++) {
        tot += g_pt[t * N_ROWS + i];
        msk += g_pm[t * N_ROWS + i];
    }
    int tg = load_tgt(targets, i, g_meta[0]);
    float cnt = (float)(QK - g_hist[tg]);
    g_row[i] = logf((tot - msk) / cnt);
}

// ---------------- k_final: deterministic sum of 2048 row terms ----------------
__global__ void k_final(float* __restrict__ out) {
    __shared__ float red[1024];
    int tid = threadIdx.x;  // 1024
    red[tid] = g_row[tid] + g_row[tid + 1024];
    __syncthreads();
    for (int s = 512; s > 0; s >>= 1) {
        if (tid < s) red[tid] += red[tid + s];
        __syncthreads();
    }
    if (tid == 0) out[0] = red[0] / (float)N_ROWS;
}

// ---------------- launch ----------------
extern "C" void kernel_launch(void* const* d_in, const int* in_sizes, int n_in,
                              void* d_out, int out_size) {
    const float* x       = (const float*)d_in[0];
    const float* q       = (const float*)d_in[1];
    const void*  targets = d_in[2];
    const void*  q_tgts  = d_in[3];
    const void*  order_p = d_in[4];

    cudaFuncSetAttribute(k_main, cudaFuncAttributeMaxDynamicSharedMemorySize, SMEM_BYTES);

    k_init<<<1, 32>>>(targets, q_tgts, order_p);
    {
        int total_warps = N_ROWS + QK;              // 26624
        int blocks = (total_warps + 7) / 8;
        k_convert<<<blocks, 256>>>(x, q);
    }
    k_hist<<<(KQ + 255) / 256, 256>>>(q_tgts);
    dim3 grid(NJT, N_ROWS / BM);                    // 192 x 16
    k_main<<<grid, 256, SMEM_BYTES>>>(targets, q_tgts);
    k_rows<<<N_ROWS / 256, 256>>>(targets);
    k_final<<<1, 1024>>>((float*)d_out);
}

// round 10
// speedup vs baseline: 7.6902x; 1.0160x over previous
#include <cuda_runtime.h>
#include <cuda_bf16.h>
#include <math.h>
#include <stdint.h>

// ---------------- problem shapes ----------------
#define N_ROWS   2048
#define DIM      512
#define NQ       3
#define KQ       8192
#define QK       (NQ * KQ)        // 24576
#define NCLS     16

// ---------------- GEMM tiling -------------------
#define BM   128                  // x rows per CTA
#define BN   128                  // q rows per CTA
#define BK   64                   // bf16 K per stage (128B rows = SW128 atom)
#define NJT  (QK / BN)            // 192 j-tiles
#define NT   (DIM / BK)           // 8 mainloop iters
#define NSTG 3

#define A_ST (BM * BK * 2)        // 16384 bytes/stage
#define B_ST (BN * BK * 2)        // 16384 bytes/stage
#define QTP_OFF  (NSTG * (A_ST + B_ST))         // 98304
#define RED_OFF  (QTP_OFF + 512)
#define RED_PITCH 5
#define SMEM_BYTES (RED_OFF + 2 * BM * RED_PITCH * 4)   // ~104KB

// ---------------- static device scratch ----------------
__device__ __align__(16) __nv_bfloat16 g_xb[N_ROWS * DIM];
__device__ __align__(16) __nv_bfloat16 g_qb[QK * DIM];
__device__ float g_pt[NJT * N_ROWS];
__device__ float g_pm[NJT * N_ROWS];
__device__ float g_row[N_ROWS];
__device__ int   g_hist[NCLS];
__device__ int   g_meta[4];   // [0]=targets is64, [1]=q_targets is64, [2]=order

__device__ __forceinline__ int load_tgt(const void* p, int i, int is64) {
    if (is64) return (int)((const long long*)p)[i];
    return ((const int*)p)[i];
}

// ---------------- helpers ----------------
__device__ __forceinline__ uint32_t smem_u32(const void* p) {
    uint32_t a;
    asm("{ .reg .u64 t; cvta.to.shared.u64 t, %1; cvt.u32.u64 %0, t; }" : "=r"(a) : "l"(p));
    return a;
}
__device__ __forceinline__ uint32_t swz(uint32_t o) { return o ^ ((o >> 3) & 0x70u); }

__device__ __forceinline__ void cpasync16(uint32_t s, const void* g) {
    asm volatile("cp.async.cg.shared.global [%0], [%1], 16;" :: "r"(s), "l"(g) : "memory");
}
__device__ __forceinline__ void cp_commit() {
    asm volatile("cp.async.commit_group;" ::: "memory");
}
__device__ __forceinline__ void ldm4(uint32_t a, uint32_t& r0, uint32_t& r1,
                                     uint32_t& r2, uint32_t& r3) {
    asm volatile("ldmatrix.sync.aligned.m8n8.x4.shared.b16 {%0,%1,%2,%3}, [%4];"
                 : "=r"(r0), "=r"(r1), "=r"(r2), "=r"(r3) : "r"(a));
}
__device__ __forceinline__ void mma16816(float* c, const uint32_t* a, const uint32_t* b) {
    asm volatile(
        "mma.sync.aligned.m16n8k16.row.col.f32.bf16.bf16.f32 "
        "{%0,%1,%2,%3}, {%4,%5,%6,%7}, {%8,%9}, {%0,%1,%2,%3};"
        : "+f"(c[0]), "+f"(c[1]), "+f"(c[2]), "+f"(c[3])
        : "r"(a[0]), "r"(a[1]), "r"(a[2]), "r"(a[3]), "r"(b[0]), "r"(b[1]));
}

// ---------------- k_init ----------------
__global__ void k_init(const void* targets, const void* q_targets, const void* order_p) {
    int t = threadIdx.x;  // 32 threads
    unsigned v = ((const unsigned*)targets)[2 * t + 1];
    unsigned any = __ballot_sync(0xffffffffu, v != 0u);
    if (t == 0) g_meta[0] = (any == 0u) ? 1 : 0;
    unsigned w = ((const unsigned*)q_targets)[2 * t + 1];
    unsigned anyq = __ballot_sync(0xffffffffu, w != 0u);
    if (t == 0) g_meta[1] = (anyq == 0u) ? 1 : 0;
    if (t == 0) g_meta[2] = ((const int*)order_p)[0];
    if (t < NCLS) g_hist[t] = 0;
}

// ---------------- k_convert: L2-norm + bf16 cast ----------------
__global__ void k_convert(const float* __restrict__ x, const float* __restrict__ q) {
    int warp = (blockIdx.x * blockDim.x + threadIdx.x) >> 5;
    int lane = threadIdx.x & 31;
    if (warp >= N_ROWS + QK) return;
    const float* src;
    __nv_bfloat16* dst;
    if (warp < N_ROWS) { src = x + (size_t)warp * DIM; dst = g_xb + (size_t)warp * DIM; }
    else { src = q + (size_t)(warp - N_ROWS) * DIM; dst = g_qb + (size_t)(warp - N_ROWS) * DIM; }
    const float2* s2 = (const float2*)src;
    float2 v[8];
    float s = 0.f;
    #pragma unroll
    for (int c = 0; c < 8; c++) {
        v[c] = s2[lane + c * 32];
        s += v[c].x * v[c].x + v[c].y * v[c].y;
    }
    #pragma unroll
    for (int o = 16; o > 0; o >>= 1) s += __shfl_xor_sync(0xffffffffu, s, o);
    float inv = 1.f / fmaxf(sqrtf(s), 1e-12f);
    __nv_bfloat162* d2 = (__nv_bfloat162*)dst;
    #pragma unroll
    for (int c = 0; c < 8; c++) {
        __nv_bfloat162 b;
        b.x = __float2bfloat16_rn(v[c].x * inv);
        b.y = __float2bfloat16_rn(v[c].y * inv);
        d2[lane + c * 32] = b;
    }
}

// ---------------- k_hist ----------------
__global__ void k_hist(const void* q_targets) {
    int i = blockIdx.x * blockDim.x + threadIdx.x;
    if (i >= KQ) return;
    int v = load_tgt(q_targets, g_meta[2] * KQ + i, g_meta[1]);
    atomicAdd(&g_hist[v], 1);
}

// ---------------- k_main: HMMA bf16 GEMM + fused exp epilogue ----------------
__global__ void __launch_bounds__(256, 2)
k_main(const void* __restrict__ targets, const void* __restrict__ q_targets) {
    extern __shared__ char smem_raw[];
    const uint32_t smem = smem_u32(smem_raw);
    const uint32_t aBase = smem;
    const uint32_t bBase = smem + NSTG * A_ST;
    int*   qtp  = (int*)(smem_raw + QTP_OFF);
    float* sm_s = (float*)(smem_raw + RED_OFF);
    float* sm_m = sm_s + BM * RED_PITCH;

    const int tid  = threadIdx.x;
    const int wid  = tid >> 5;
    const int lane = tid & 31;
    const int wm   = wid & 1;          // 2 warp-rows (64 M each)
    const int wn   = wid >> 1;         // 4 warp-cols (32 N each)
    const int i0   = blockIdx.y * BM;
    const int j0   = blockIdx.x * BN;

    const int is64t = g_meta[0];
    const int is64q = g_meta[1];
    const bool otile = (j0 / KQ) == g_meta[2];

    if (otile && tid < BN) qtp[tid] = load_tgt(q_targets, j0 + tid, is64q);

    // per-thread cp.async dest/src bases (immediate offsets per stage after unroll)
    uint32_t dstA[4];
    const char* srcA[4];
    const char* srcB[4];
    #pragma unroll
    for (int l = 0; l < 4; l++) {
        int idx = tid + l * 256, row = idx >> 3, c = idx & 7;
        dstA[l] = swz((uint32_t)(row * 128 + c * 16));
        srcA[l] = (const char*)(g_xb + ((size_t)(i0 + row) * DIM + c * 8));
        srcB[l] = (const char*)(g_qb + ((size_t)(j0 + row) * DIM + c * 8));
    }

    // ldmatrix per-lane byte offsets within a stage (ks -> XOR ks*32)
    uint32_t offA0[4], offB0[2];
    {
        int kc = lane >> 4;                 // 16B half
        #pragma unroll
        for (int m = 0; m < 4; m++) {
            int rowA = wm * 64 + m * 16 + (lane & 15);
            offA0[m] = swz((uint32_t)(rowA * 128 + kc * 16));
        }
        int kc2 = (lane >> 3) & 1;
        #pragma unroll
        for (int p = 0; p < 2; p++) {
            int rowB = wn * 32 + p * 16 + (lane & 7) + ((lane >> 4) & 1) * 8;
            offB0[p] = swz((uint32_t)(rowB * 128 + kc2 * 16));
        }
    }

    // hoisted epilogue row-target loads (hide ~600cyc behind the GEMM)
    const int l4  = lane >> 2;
    const int lm4 = lane & 3;
    int tgr[8];
    #pragma unroll
    for (int m = 0; m < 4; m++)
        #pragma unroll
        for (int half = 0; half < 2; half++)
            tgr[m * 2 + half] = load_tgt(targets, i0 + wm * 64 + m * 16 + half * 8 + l4, is64t);

    float c[4][4][4];
    #pragma unroll
    for (int m = 0; m < 4; m++)
        #pragma unroll
        for (int n = 0; n < 4; n++)
            #pragma unroll
            for (int e = 0; e < 4; e++) c[m][n][e] = 0.f;

    // register-double-buffered fragments
    uint32_t afr[2][4][4], bfr[2][4][2];

    // ---- prologue: stages 0,1 ----
    #pragma unroll
    for (int s = 0; s < 2; s++) {
        #pragma unroll
        for (int l = 0; l < 4; l++) cpasync16(aBase + s * A_ST + dstA[l], srcA[l] + s * 128);
        #pragma unroll
        for (int l = 0; l < 4; l++) cpasync16(bBase + s * B_ST + dstA[l], srcB[l] + s * 128);
        cp_commit();
    }

    #pragma unroll
    for (int kt = 0; kt < NT; kt++) {
        if (kt < NT - 1) asm volatile("cp.async.wait_group 1;" ::: "memory");
        else             asm volatile("cp.async.wait_group 0;" ::: "memory");
        __syncthreads();

        if (kt + 2 < NT) {
            const int s = (kt + 2) % NSTG;           // compile-time under unroll
            #pragma unroll
            for (int l = 0; l < 4; l++) cpasync16(aBase + s * A_ST + dstA[l], srcA[l] + (kt + 2) * 128);
            #pragma unroll
            for (int l = 0; l < 4; l++) cpasync16(bBase + s * B_ST + dstA[l], srcB[l] + (kt + 2) * 128);
            cp_commit();
        }

        const uint32_t aS = aBase + (kt % NSTG) * A_ST;
        const uint32_t bS = bBase + (kt % NSTG) * B_ST;

        // load ks=0 fragments into buffer 0
        #pragma unroll
        for (int m = 0; m < 4; m++)
            ldm4(aS + offA0[m], afr[0][m][0], afr[0][m][1], afr[0][m][2], afr[0][m][3]);
        #pragma unroll
        for (int p = 0; p < 2; p++)
            ldm4(bS + offB0[p], bfr[0][2*p][0], bfr[0][2*p][1], bfr[0][2*p+1][0], bfr[0][2*p+1][1]);

        #pragma unroll
        for (int ks = 0; ks < 4; ks++) {
            const int cur = ks & 1;
            if (ks < 3) {
                const int nxt = cur ^ 1;
                const uint32_t kx = (ks + 1) * 32;
                #pragma unroll
                for (int m = 0; m < 4; m++)
                    ldm4(aS + (offA0[m] ^ kx), afr[nxt][m][0], afr[nxt][m][1],
                         afr[nxt][m][2], afr[nxt][m][3]);
                #pragma unroll
                for (int p = 0; p < 2; p++)
                    ldm4(bS + (offB0[p] ^ kx), bfr[nxt][2*p][0], bfr[nxt][2*p][1],
                         bfr[nxt][2*p+1][0], bfr[nxt][2*p+1][1]);
            }
            #pragma unroll
            for (int m = 0; m < 4; m++)
                #pragma unroll
                for (int n = 0; n < 4; n++)
                    mma16816(c[m][n], afr[cur][m], bfr[cur][n]);
        }
    }

    // ---- epilogue: exp + per-row (total, masked) partial sums ----
    int qtv[8];
    if (otile) {
        #pragma unroll
        for (int n = 0; n < 4; n++)
            #pragma unroll
            for (int e = 0; e < 2; e++)
                qtv[n * 2 + e] = qtp[wn * 32 + n * 8 + lm4 * 2 + e];
    }
    #pragma unroll
    for (int m = 0; m < 4; m++) {
        #pragma unroll
        for (int half = 0; half < 2; half++) {
            const int rl = wm * 64 + m * 16 + half * 8 + l4;   // local row
            const int tg = tgr[m * 2 + half];
            float s = 0.f, mk = 0.f;
            #pragma unroll
            for (int n = 0; n < 4; n++) {
                #pragma unroll
                for (int e = 0; e < 2; e++) {
                    float ex = __expf(fmaf(4.f, c[m][n][half * 2 + e], -4.f));
                    s += ex;
                    if (otile && qtv[n * 2 + e] == tg) mk += ex;
                }
            }
            s  += __shfl_xor_sync(0xffffffffu, s, 1);
            s  += __shfl_xor_sync(0xffffffffu, s, 2);
            mk += __shfl_xor_sync(0xffffffffu, mk, 1);
            mk += __shfl_xor_sync(0xffffffffu, mk, 2);
            if (lm4 == 0) {
                sm_s[rl * RED_PITCH + wn] = s;
                sm_m[rl * RED_PITCH + wn] = mk;
            }
        }
    }
    __syncthreads();
    if (tid < BM) {
        float tot = 0.f, msk = 0.f;
        #pragma unroll
        for (int w = 0; w < 4; w++) {
            tot += sm_s[tid * RED_PITCH + w];
            msk += sm_m[tid * RED_PITCH + w];
        }
        g_pt[blockIdx.x * N_ROWS + i0 + tid] = tot;
        g_pm[blockIdx.x * N_ROWS + i0 + tid] = msk;
    }
}

// ---------------- k_rows: per-row log terms (parallel) ----------------
__global__ void k_rows(const void* __restrict__ targets) {
    int i = blockIdx.x * blockDim.x + threadIdx.x;   // 8 x 256 = 2048
    float t0 = 0.f, t1 = 0.f, m0 = 0.f, m1 = 0.f;
    #pragma unroll 4
    for (int t = 0; t < NJT; t += 2) {
        t0 += g_pt[t * N_ROWS + i];
        t1 += g_pt[(t + 1) * N_ROWS + i];
        m0 += g_pm[t * N_ROWS + i];
        m1 += g_pm[(t + 1) * N_ROWS + i];
    }
    int tg = load_tgt(targets, i, g_meta[0]);
    float cnt = (float)(QK - g_hist[tg]);
    g_row[i] = logf(((t0 + t1) - (m0 + m1)) / cnt);
}

// ---------------- k_final: deterministic sum of 2048 row terms ----------------
__global__ void k_final(float* __restrict__ out) {
    __shared__ float red[1024];
    int tid = threadIdx.x;  // 1024
    red[tid] = g_row[tid] + g_row[tid + 1024];
    __syncthreads();
    for (int s = 512; s > 0; s >>= 1) {
        if (tid < s) red[tid] += red[tid + s];
        __syncthreads();
    }
    if (tid == 0) out[0] = red[0] / (float)N_ROWS;
}

// ---------------- launch ----------------
extern "C" void kernel_launch(void* const* d_in, const int* in_sizes, int n_in,
                              void* d_out, int out_size) {
    const float* x       = (const float*)d_in[0];
    const float* q       = (const float*)d_in[1];
    const void*  targets = d_in[2];
    const void*  q_tgts  = d_in[3];
    const void*  order_p = d_in[4];

    cudaFuncSetAttribute(k_main, cudaFuncAttributeMaxDynamicSharedMemorySize, SMEM_BYTES);

    k_init<<<1, 32>>>(targets, q_tgts, order_p);
    {
        int total_warps = N_ROWS + QK;              // 26624
        int blocks = (total_warps + 7) / 8;
        k_convert<<<blocks, 256>>>(x, q);
    }
    k_hist<<<(KQ + 255) / 256, 256>>>(q_tgts);
    dim3 grid(NJT, N_ROWS / BM);                    // 192 x 16
    k_main<<<grid, 256, SMEM_BYTES>>>(targets, q_tgts);
    k_rows<<<N_ROWS / 256, 256>>>(targets);
    k_final<<<1, 1024>>>((float*)d_out);
}

// round 14
// speedup vs baseline: 7.7158x; 1.0033x over previous
#include <cuda_runtime.h>
#include <cuda_bf16.h>
#include <math.h>
#include <stdint.h>

// ---------------- problem shapes ----------------
#define N_ROWS   2048
#define DIM      512
#define NQ       3
#define KQ       8192
#define QK       (NQ * KQ)        // 24576
#define NCLS     16

// ---------------- GEMM tiling -------------------
#define BM   128                  // x rows per CTA
#define BN   128                  // q rows per CTA
#define BK   64                   // bf16 K per stage (128B rows = SW128 atom)
#define NJT  (QK / BN)            // 192 j-tiles
#define NT   (DIM / BK)           // 8 mainloop iters
#define NSTG 3

#define A_ST (BM * BK * 2)        // 16384 bytes/stage
#define B_ST (BN * BK * 2)        // 16384 bytes/stage
#define QTP_OFF  (NSTG * (A_ST + B_ST))         // 98304
#define RED_OFF  (QTP_OFF + 512)
#define RED_PITCH 5
#define SMEM_BYTES (RED_OFF + 2 * BM * RED_PITCH * 4)   // ~104KB

// ---------------- static device scratch ----------------
__device__ __align__(16) __nv_bfloat16 g_xb[N_ROWS * DIM];
__device__ __align__(16) __nv_bfloat16 g_qb[QK * DIM];
__device__ float g_pt[NJT * N_ROWS];
__device__ float g_pm[NJT * N_ROWS];
__device__ float g_row[N_ROWS];
__device__ int   g_hist[NCLS];
__device__ int   g_meta[4];   // [0]=targets is64, [1]=q_targets is64, [2]=order

__device__ __forceinline__ int load_tgt(const void* p, int i, int is64) {
    if (is64) return (int)((const long long*)p)[i];
    return ((const int*)p)[i];
}

// ---------------- helpers ----------------
__device__ __forceinline__ uint32_t smem_u32(const void* p) {
    uint32_t a;
    asm("{ .reg .u64 t; cvta.to.shared.u64 t, %1; cvt.u32.u64 %0, t; }" : "=r"(a) : "l"(p));
    return a;
}
__device__ __forceinline__ uint32_t swz(uint32_t o) { return o ^ ((o >> 3) & 0x70u); }

__device__ __forceinline__ void cpasync16(uint32_t s, const void* g) {
    asm volatile("cp.async.cg.shared.global [%0], [%1], 16;" :: "r"(s), "l"(g) : "memory");
}
__device__ __forceinline__ void cp_commit() {
    asm volatile("cp.async.commit_group;" ::: "memory");
}
__device__ __forceinline__ void cp_wait0() {
    asm volatile("cp.async.wait_group 0;" ::: "memory");
}
__device__ __forceinline__ void ldm4(uint32_t a, uint32_t& r0, uint32_t& r1,
                                     uint32_t& r2, uint32_t& r3) {
    asm volatile("ldmatrix.sync.aligned.m8n8.x4.shared.b16 {%0,%1,%2,%3}, [%4];"
                 : "=r"(r0), "=r"(r1), "=r"(r2), "=r"(r3) : "r"(a));
}
__device__ __forceinline__ void mma16816(float* c, const uint32_t* a, const uint32_t* b) {
    asm volatile(
        "mma.sync.aligned.m16n8k16.row.col.f32.bf16.bf16.f32 "
        "{%0,%1,%2,%3}, {%4,%5,%6,%7}, {%8,%9}, {%0,%1,%2,%3};"
        : "+f"(c[0]), "+f"(c[1]), "+f"(c[2]), "+f"(c[3])
        : "r"(a[0]), "r"(a[1]), "r"(a[2]), "r"(a[3]), "r"(b[0]), "r"(b[1]));
}

// ---------------- k_init ----------------
__global__ void k_init(const void* targets, const void* q_targets, const void* order_p) {
    int t = threadIdx.x;  // 32 threads
    unsigned v = ((const unsigned*)targets)[2 * t + 1];
    unsigned any = __ballot_sync(0xffffffffu, v != 0u);
    if (t == 0) g_meta[0] = (any == 0u) ? 1 : 0;
    unsigned w = ((const unsigned*)q_targets)[2 * t + 1];
    unsigned anyq = __ballot_sync(0xffffffffu, w != 0u);
    if (t == 0) g_meta[1] = (anyq == 0u) ? 1 : 0;
    if (t == 0) g_meta[2] = ((const int*)order_p)[0];
    if (t < NCLS) g_hist[t] = 0;
}

// ---------------- k_convert: L2-norm + bf16 cast (float4 loads) ----------------
__global__ void k_convert(const float* __restrict__ x, const float* __restrict__ q) {
    int warp = (blockIdx.x * blockDim.x + threadIdx.x) >> 5;
    int lane = threadIdx.x & 31;
    if (warp >= N_ROWS + QK) return;
    const float* src;
    __nv_bfloat16* dst;
    if (warp < N_ROWS) { src = x + (size_t)warp * DIM; dst = g_xb + (size_t)warp * DIM; }
    else { src = q + (size_t)(warp - N_ROWS) * DIM; dst = g_qb + (size_t)(warp - N_ROWS) * DIM; }
    const float4* s4 = (const float4*)src;
    float4 v[4];
    float s = 0.f;
    #pragma unroll
    for (int c = 0; c < 4; c++) {
        v[c] = s4[lane + c * 32];
        s += v[c].x * v[c].x + v[c].y * v[c].y + v[c].z * v[c].z + v[c].w * v[c].w;
    }
    #pragma unroll
    for (int o = 16; o > 0; o >>= 1) s += __shfl_xor_sync(0xffffffffu, s, o);
    float inv = 1.f / fmaxf(sqrtf(s), 1e-12f);
    uint2* d2 = (uint2*)dst;
    #pragma unroll
    for (int c = 0; c < 4; c++) {
        __nv_bfloat162 lo, hi;
        lo.x = __float2bfloat16_rn(v[c].x * inv);
        lo.y = __float2bfloat16_rn(v[c].y * inv);
        hi.x = __float2bfloat16_rn(v[c].z * inv);
        hi.y = __float2bfloat16_rn(v[c].w * inv);
        uint2 o2;
        o2.x = *(uint32_t*)&lo;
        o2.y = *(uint32_t*)&hi;
        d2[lane + c * 32] = o2;
    }
}

// ---------------- k_hist ----------------
__global__ void k_hist(const void* q_targets) {
    int i = blockIdx.x * blockDim.x + threadIdx.x;
    if (i >= KQ) return;
    int v = load_tgt(q_targets, g_meta[2] * KQ + i, g_meta[1]);
    atomicAdd(&g_hist[v], 1);
}

// ---------------- k_main: HMMA bf16 GEMM + fused exp epilogue ----------------
__global__ void __launch_bounds__(256, 2)
k_main(const void* __restrict__ targets, const void* __restrict__ q_targets) {
    extern __shared__ char smem_raw[];
    const uint32_t smem = smem_u32(smem_raw);
    const uint32_t aBase = smem;
    const uint32_t bBase = smem + NSTG * A_ST;
    int*   qtp  = (int*)(smem_raw + QTP_OFF);
    float* sm_s = (float*)(smem_raw + RED_OFF);
    float* sm_m = sm_s + BM * RED_PITCH;

    const int tid  = threadIdx.x;
    const int wid  = tid >> 5;
    const int lane = tid & 31;
    const int wm   = wid & 1;          // 2 warp-rows (64 M each)
    const int wn   = wid >> 1;         // 4 warp-cols (32 N each)
    const int i0   = blockIdx.y * BM;
    const int j0   = blockIdx.x * BN;

    const int is64t = g_meta[0];
    const int is64q = g_meta[1];
    const bool otile = (j0 / KQ) == g_meta[2];

    if (otile && tid < BN) qtp[tid] = load_tgt(q_targets, j0 + tid, is64q);

    // per-thread cp.async dest/src bases (immediate offsets per stage after unroll)
    uint32_t dstA[4];
    const char* srcA[4];
    const char* srcB[4];
    #pragma unroll
    for (int l = 0; l < 4; l++) {
        int idx = tid + l * 256, row = idx >> 3, c = idx & 7;
        dstA[l] = swz((uint32_t)(row * 128 + c * 16));
        srcA[l] = (const char*)(g_xb + ((size_t)(i0 + row) * DIM + c * 8));
        srcB[l] = (const char*)(g_qb + ((size_t)(j0 + row) * DIM + c * 8));
    }

    // ldmatrix per-lane byte offsets within a stage (ks -> XOR ks*32)
    uint32_t offA0[4], offB0[2];
    {
        int kc = lane >> 4;                 // 16B half
        #pragma unroll
        for (int m = 0; m < 4; m++) {
            int rowA = wm * 64 + m * 16 + (lane & 15);
            offA0[m] = swz((uint32_t)(rowA * 128 + kc * 16));
        }
        int kc2 = (lane >> 3) & 1;
        #pragma unroll
        for (int p = 0; p < 2; p++) {
            int rowB = wn * 32 + p * 16 + (lane & 7) + ((lane >> 4) & 1) * 8;
            offB0[p] = swz((uint32_t)(rowB * 128 + kc2 * 16));
        }
    }

    // hoisted epilogue row-target loads (hide latency behind the GEMM)
    const int l4  = lane >> 2;
    const int lm4 = lane & 3;
    int tgr[8];
    #pragma unroll
    for (int m = 0; m < 4; m++)
        #pragma unroll
        for (int half = 0; half < 2; half++)
            tgr[m * 2 + half] = load_tgt(targets, i0 + wm * 64 + m * 16 + half * 8 + l4, is64t);

    float c[4][4][4];
    #pragma unroll
    for (int m = 0; m < 4; m++)
        #pragma unroll
        for (int n = 0; n < 4; n++)
            #pragma unroll
            for (int e = 0; e < 4; e++) c[m][n][e] = 0.f;

    // register-double-buffered fragments
    uint32_t afr[2][4][4], bfr[2][4][2];

    // ---- prologue: stages 0,1; wait both, sync, preload ks0 of stage 0 ----
    #pragma unroll
    for (int s = 0; s < 2; s++) {
        #pragma unroll
        for (int l = 0; l < 4; l++) cpasync16(aBase + s * A_ST + dstA[l], srcA[l] + s * 128);
        #pragma unroll
        for (int l = 0; l < 4; l++) cpasync16(bBase + s * B_ST + dstA[l], srcB[l] + s * 128);
        cp_commit();
    }
    cp_wait0();
    __syncthreads();
    #pragma unroll
    for (int m = 0; m < 4; m++)
        ldm4(aBase + offA0[m], afr[0][m][0], afr[0][m][1], afr[0][m][2], afr[0][m][3]);
    #pragma unroll
    for (int p = 0; p < 2; p++)
        ldm4(bBase + offB0[p], bfr[0][2*p][0], bfr[0][2*p][1], bfr[0][2*p+1][0], bfr[0][2*p+1][1]);

    #pragma unroll
    for (int kt = 0; kt < NT; kt++) {
        const uint32_t aS = aBase + (kt % NSTG) * A_ST;
        const uint32_t bS = bBase + (kt % NSTG) * B_ST;
        const uint32_t aN = aBase + ((kt + 1) % NSTG) * A_ST;   // next stage (data already resident)
        const uint32_t bN = bBase + ((kt + 1) % NSTG) * B_ST;

        #pragma unroll
        for (int ks = 0; ks < 4; ks++) {
            const int cur = ks & 1;
            const int nxt = cur ^ 1;
            if (ks < 3) {
                const uint32_t kx = (ks + 1) * 32;
                #pragma unroll
                for (int m = 0; m < 4; m++)
                    ldm4(aS + (offA0[m] ^ kx), afr[nxt][m][0], afr[nxt][m][1],
                         afr[nxt][m][2], afr[nxt][m][3]);
                #pragma unroll
                for (int p = 0; p < 2; p++)
                    ldm4(bS + (offB0[p] ^ kx), bfr[nxt][2*p][0], bfr[nxt][2*p][1],
                         bfr[nxt][2*p+1][0], bfr[nxt][2*p+1][1]);
            } else if (kt + 1 < NT) {
                // cross-iteration prefetch: ks=0 fragments of stage kt+1 (visible
                // since bottom-of-(kt-1) wait_group 0 + barrier)
                #pragma unroll
                for (int m = 0; m < 4; m++)
                    ldm4(aN + offA0[m], afr[nxt][m][0], afr[nxt][m][1],
                         afr[nxt][m][2], afr[nxt][m][3]);
                #pragma unroll
                for (int p = 0; p < 2; p++)
                    ldm4(bN + offB0[p], bfr[nxt][2*p][0], bfr[nxt][2*p][1],
                         bfr[nxt][2*p+1][0], bfr[nxt][2*p+1][1]);
            }
            #pragma unroll
            for (int m = 0; m < 4; m++)
                #pragma unroll
                for (int n = 0; n < 4; n++)
                    mma16816(c[m][n], afr[cur][m], bfr[cur][n]);

            // issue next-stage global prefetch after ks0's MMAs (LDSM-priority)
            if (ks == 0 && kt + 2 < NT) {
                const int s = (kt + 2) % NSTG;
                #pragma unroll
                for (int l = 0; l < 4; l++) cpasync16(aBase + s * A_ST + dstA[l], srcA[l] + (kt + 2) * 128);
                #pragma unroll
                for (int l = 0; l < 4; l++) cpasync16(bBase + s * B_ST + dstA[l], srcB[l] + (kt + 2) * 128);
                cp_commit();
            }
        }

        if (kt + 1 < NT) {
            cp_wait0();          // stage kt+2 resident (issued ~1 iter ago)
            __syncthreads();     // protect stage reuse + cross-thread visibility
        }
    }

    // ---- epilogue: exp + per-row (total, masked) partial sums ----
    int qtv[8];
    if (otile) {
        #pragma unroll
        for (int n = 0; n < 4; n++)
            #pragma unroll
            for (int e = 0; e < 2; e++)
                qtv[n * 2 + e] = qtp[wn * 32 + n * 8 + lm4 * 2 + e];
    }
    #pragma unroll
    for (int m = 0; m < 4; m++) {
        #pragma unroll
        for (int half = 0; half < 2; half++) {
            const int rl = wm * 64 + m * 16 + half * 8 + l4;   // local row
            const int tg = tgr[m * 2 + half];
            float s = 0.f, mk = 0.f;
            #pragma unroll
            for (int n = 0; n < 4; n++) {
                #pragma unroll
                for (int e = 0; e < 2; e++) {
                    float ex = __expf(fmaf(4.f, c[m][n][half * 2 + e], -4.f));
                    s += ex;
                    if (otile && qtv[n * 2 + e] == tg) mk += ex;
                }
            }
            s  += __shfl_xor_sync(0xffffffffu, s, 1);
            s  += __shfl_xor_sync(0xffffffffu, s, 2);
            mk += __shfl_xor_sync(0xffffffffu, mk, 1);
            mk += __shfl_xor_sync(0xffffffffu, mk, 2);
            if (lm4 == 0) {
                sm_s[rl * RED_PITCH + wn] = s;
                sm_m[rl * RED_PITCH + wn] = mk;
            }
        }
    }
    __syncthreads();
    if (tid < BM) {
        float tot = 0.f, msk = 0.f;
        #pragma unroll
        for (int w = 0; w < 4; w++) {
            tot += sm_s[tid * RED_PITCH + w];
            msk += sm_m[tid * RED_PITCH + w];
        }
        g_pt[blockIdx.x * N_ROWS + i0 + tid] = tot;
        g_pm[blockIdx.x * N_ROWS + i0 + tid] = msk;
    }
}

// ---------------- k_rows: per-row log terms (parallel) ----------------
__global__ void k_rows(const void* __restrict__ targets) {
    int i = blockIdx.x * blockDim.x + threadIdx.x;   // 8 x 256 = 2048
    float t0 = 0.f, t1 = 0.f, m0 = 0.f, m1 = 0.f;
    #pragma unroll 4
    for (int t = 0; t < NJT; t += 2) {
        t0 += g_pt[t * N_ROWS + i];
        t1 += g_pt[(t + 1) * N_ROWS + i];
        m0 += g_pm[t * N_ROWS + i];
        m1 += g_pm[(t + 1) * N_ROWS + i];
    }
    int tg = load_tgt(targets, i, g_meta[0]);
    float cnt = (float)(QK - g_hist[tg]);
    g_row[i] = logf(((t0 + t1) - (m0 + m1)) / cnt);
}

// ---------------- k_final: deterministic sum of 2048 row terms ----------------
__global__ void k_final(float* __restrict__ out) {
    __shared__ float red[1024];
    int tid = threadIdx.x;  // 1024
    red[tid] = g_row[tid] + g_row[tid + 1024];
    __syncthreads();
    for (int s = 512; s > 0; s >>= 1) {
        if (tid < s) red[tid] += red[tid + s];
        __syncthreads();
    }
    if (tid == 0) out[0] = red[0] / (float)N_ROWS;
}

// ---------------- launch ----------------
extern "C" void kernel_launch(void* const* d_in, const int* in_sizes, int n_in,
                              void* d_out, int out_size) {
    const float* x       = (const float*)d_in[0];
    const float* q       = (const float*)d_in[1];
    const void*  targets = d_in[2];
    const void*  q_tgts  = d_in[3];
    const void*  order_p = d_in[4];

    cudaFuncSetAttribute(k_main, cudaFuncAttributeMaxDynamicSharedMemorySize, SMEM_BYTES);

    k_init<<<1, 32>>>(targets, q_tgts, order_p);
    {
        int total_warps = N_ROWS + QK;              // 26624
        int blocks = (total_warps + 7) / 8;
        k_convert<<<blocks, 256>>>(x, q);
    }
    k_hist<<<(KQ + 255) / 256, 256>>>(q_tgts);
    dim3 grid(NJT, N_ROWS / BM);                    // 192 x 16
    k_main<<<grid, 256, SMEM_BYTES>>>(targets, q_tgts);
    k_rows<<<N_ROWS / 256, 256>>>(targets);
    k_final<<<1, 1024>>>((float*)d_out);
}

// round 15
// speedup vs baseline: 7.7920x; 1.0099x over previous
#include <cuda_runtime.h>
#include <cuda_bf16.h>
#include <math.h>
#include <stdint.h>

// ---------------- problem shapes ----------------
#define N_ROWS   2048
#define DIM      512
#define NQ       3
#define KQ       8192
#define QK       (NQ * KQ)        // 24576
#define NCLS     16
#define NHB      32               // histogram partial blocks

// ---------------- GEMM tiling -------------------
#define BM   128                  // x rows per CTA
#define BN   128                  // q rows per CTA
#define BK   64                   // bf16 K per stage (128B rows = SW128 atom)
#define NJT  (QK / BN)            // 192 j-tiles
#define NT   (DIM / BK)           // 8 mainloop iters
#define NSTG 3

#define A_ST (BM * BK * 2)        // 16384 bytes/stage
#define B_ST (BN * BK * 2)        // 16384 bytes/stage
#define QTP_OFF  (NSTG * (A_ST + B_ST))         // 98304
#define RED_OFF  (QTP_OFF + 512)
#define RED_PITCH 5
#define SMEM_BYTES (RED_OFF + 2 * BM * RED_PITCH * 4)   // ~104KB

// ---------------- static device scratch ----------------
__device__ __align__(16) __nv_bfloat16 g_xb[N_ROWS * DIM];
__device__ __align__(16) __nv_bfloat16 g_qb[QK * DIM];
__device__ float g_pt[NJT * N_ROWS];
__device__ float g_pm[NJT * N_ROWS];
__device__ float g_row[N_ROWS];
__device__ int   g_hpart[NHB * NCLS];
__device__ int   g_meta[4];   // [0]=targets is64, [1]=q_targets is64, [2]=order
__device__ int   g_tick;

__device__ __forceinline__ int load_tgt(const void* p, int i, int is64) {
    if (is64) return (int)((const long long*)p)[i];
    return ((const int*)p)[i];
}

// ---------------- helpers ----------------
__device__ __forceinline__ uint32_t smem_u32(const void* p) {
    uint32_t a;
    asm("{ .reg .u64 t; cvta.to.shared.u64 t, %1; cvt.u32.u64 %0, t; }" : "=r"(a) : "l"(p));
    return a;
}
__device__ __forceinline__ uint32_t swz(uint32_t o) { return o ^ ((o >> 3) & 0x70u); }

__device__ __forceinline__ void cpasync16(uint32_t s, const void* g) {
    asm volatile("cp.async.cg.shared.global [%0], [%1], 16;" :: "r"(s), "l"(g) : "memory");
}
__device__ __forceinline__ void cp_commit() {
    asm volatile("cp.async.commit_group;" ::: "memory");
}
__device__ __forceinline__ void cp_wait0() {
    asm volatile("cp.async.wait_group 0;" ::: "memory");
}
__device__ __forceinline__ void ldm4(uint32_t a, uint32_t& r0, uint32_t& r1,
                                     uint32_t& r2, uint32_t& r3) {
    asm volatile("ldmatrix.sync.aligned.m8n8.x4.shared.b16 {%0,%1,%2,%3}, [%4];"
                 : "=r"(r0), "=r"(r1), "=r"(r2), "=r"(r3) : "r"(a));
}
__device__ __forceinline__ void mma16816(float* c, const uint32_t* a, const uint32_t* b) {
    asm volatile(
        "mma.sync.aligned.m16n8k16.row.col.f32.bf16.bf16.f32 "
        "{%0,%1,%2,%3}, {%4,%5,%6,%7}, {%8,%9}, {%0,%1,%2,%3};"
        : "+f"(c[0]), "+f"(c[1]), "+f"(c[2]), "+f"(c[3])
        : "r"(a[0]), "r"(a[1]), "r"(a[2]), "r"(a[3]), "r"(b[0]), "r"(b[1]));
}

// ---------------- k_pre: meta detection + histogram partials ----------------
// Blocks 0..31: per-block smem histogram of q_targets[order] -> g_hpart (stores,
// no global zeroing needed; each block re-derives is64q/order locally).
// Block 32: targets dtype probe.
__global__ void k_pre(const void* targets, const void* q_targets, const void* order_p) {
    const int b = blockIdx.x, tid = threadIdx.x;
    if (b == NHB) {
        if (tid < 32) {
            unsigned v = ((const unsigned*)targets)[2 * tid + 1];
            unsigned any = __ballot_sync(0xffffffffu, v != 0u);
            if (tid == 0) g_meta[0] = (any == 0u) ? 1 : 0;
        }
        return;
    }
    __shared__ int hist_s[NCLS];
    // local dtype/order detection (identical result in every block)
    unsigned w = ((const unsigned*)q_targets)[2 * (tid & 31) + 1];
    unsigned anyq = __ballot_sync(0xffffffffu, w != 0u);
    const int is64q = (anyq == 0u) ? 1 : 0;
    const int order = ((const int*)order_p)[0];   // low dword valid for i32/i64
    if (tid < NCLS) hist_s[tid] = 0;
    __syncthreads();
    const int i = b * 256 + tid;                  // 32*256 = 8192 = KQ
    int v = load_tgt(q_targets, order * KQ + i, is64q);
    atomicAdd(&hist_s[v], 1);
    __syncthreads();
    if (tid < NCLS) g_hpart[b * NCLS + tid] = hist_s[tid];
    if (b == 0 && tid == 0) { g_meta[1] = is64q; g_meta[2] = order; }
}

// ---------------- k_convert: L2-norm + bf16 cast (float4 loads) ----------------
__global__ void k_convert(const float* __restrict__ x, const float* __restrict__ q) {
    int warp = (blockIdx.x * blockDim.x + threadIdx.x) >> 5;
    int lane = threadIdx.x & 31;
    if (warp >= N_ROWS + QK) return;
    const float* src;
    __nv_bfloat16* dst;
    if (warp < N_ROWS) { src = x + (size_t)warp * DIM; dst = g_xb + (size_t)warp * DIM; }
    else { src = q + (size_t)(warp - N_ROWS) * DIM; dst = g_qb + (size_t)(warp - N_ROWS) * DIM; }
    const float4* s4 = (const float4*)src;
    float4 v[4];
    float s = 0.f;
    #pragma unroll
    for (int c = 0; c < 4; c++) {
        v[c] = s4[lane + c * 32];
        s += v[c].x * v[c].x + v[c].y * v[c].y + v[c].z * v[c].z + v[c].w * v[c].w;
    }
    #pragma unroll
    for (int o = 16; o > 0; o >>= 1) s += __shfl_xor_sync(0xffffffffu, s, o);
    float inv = 1.f / fmaxf(sqrtf(s), 1e-12f);
    uint2* d2 = (uint2*)dst;
    #pragma unroll
    for (int c = 0; c < 4; c++) {
        __nv_bfloat162 lo, hi;
        lo.x = __float2bfloat16_rn(v[c].x * inv);
        lo.y = __float2bfloat16_rn(v[c].y * inv);
        hi.x = __float2bfloat16_rn(v[c].z * inv);
        hi.y = __float2bfloat16_rn(v[c].w * inv);
        uint2 o2;
        o2.x = *(uint32_t*)&lo;
        o2.y = *(uint32_t*)&hi;
        d2[lane + c * 32] = o2;
    }
}

// ---------------- k_main: HMMA bf16 GEMM + fused exp epilogue ----------------
__global__ void __launch_bounds__(256, 2)
k_main(const void* __restrict__ targets, const void* __restrict__ q_targets) {
    extern __shared__ char smem_raw[];
    const uint32_t smem = smem_u32(smem_raw);
    const uint32_t aBase = smem;
    const uint32_t bBase = smem + NSTG * A_ST;
    int*   qtp  = (int*)(smem_raw + QTP_OFF);
    float* sm_s = (float*)(smem_raw + RED_OFF);
    float* sm_m = sm_s + BM * RED_PITCH;

    const int tid  = threadIdx.x;
    const int wid  = tid >> 5;
    const int lane = tid & 31;
    const int wm   = wid & 1;          // 2 warp-rows (64 M each)
    const int wn   = wid >> 1;         // 4 warp-cols (32 N each)
    const int i0   = blockIdx.y * BM;
    const int j0   = blockIdx.x * BN;

    const int is64t = g_meta[0];
    const int is64q = g_meta[1];
    const bool otile = (j0 / KQ) == g_meta[2];

    if (otile && tid < BN) qtp[tid] = load_tgt(q_targets, j0 + tid, is64q);

    // per-thread cp.async dest/src bases (immediate offsets per stage after unroll)
    uint32_t dstA[4];
    const char* srcA[4];
    const char* srcB[4];
    #pragma unroll
    for (int l = 0; l < 4; l++) {
        int idx = tid + l * 256, row = idx >> 3, c = idx & 7;
        dstA[l] = swz((uint32_t)(row * 128 + c * 16));
        srcA[l] = (const char*)(g_xb + ((size_t)(i0 + row) * DIM + c * 8));
        srcB[l] = (const char*)(g_qb + ((size_t)(j0 + row) * DIM + c * 8));
    }

    // ldmatrix per-lane byte offsets within a stage (ks -> XOR ks*32)
    uint32_t offA0[4], offB0[2];
    {
        int kc = lane >> 4;                 // 16B half
        #pragma unroll
        for (int m = 0; m < 4; m++) {
            int rowA = wm * 64 + m * 16 + (lane & 15);
            offA0[m] = swz((uint32_t)(rowA * 128 + kc * 16));
        }
        int kc2 = (lane >> 3) & 1;
        #pragma unroll
        for (int p = 0; p < 2; p++) {
            int rowB = wn * 32 + p * 16 + (lane & 7) + ((lane >> 4) & 1) * 8;
            offB0[p] = swz((uint32_t)(rowB * 128 + kc2 * 16));
        }
    }

    // hoisted epilogue row-target loads (hide latency behind the GEMM)
    const int l4  = lane >> 2;
    const int lm4 = lane & 3;
    int tgr[8];
    #pragma unroll
    for (int m = 0; m < 4; m++)
        #pragma unroll
        for (int half = 0; half < 2; half++)
            tgr[m * 2 + half] = load_tgt(targets, i0 + wm * 64 + m * 16 + half * 8 + l4, is64t);

    float c[4][4][4];
    #pragma unroll
    for (int m = 0; m < 4; m++)
        #pragma unroll
        for (int n = 0; n < 4; n++)
            #pragma unroll
            for (int e = 0; e < 4; e++) c[m][n][e] = 0.f;

    // register-double-buffered fragments
    uint32_t afr[2][4][4], bfr[2][4][2];

    // ---- prologue: stages 0,1; wait both, sync, preload ks0 of stage 0 ----
    #pragma unroll
    for (int s = 0; s < 2; s++) {
        #pragma unroll
        for (int l = 0; l < 4; l++) cpasync16(aBase + s * A_ST + dstA[l], srcA[l] + s * 128);
        #pragma unroll
        for (int l = 0; l < 4; l++) cpasync16(bBase + s * B_ST + dstA[l], srcB[l] + s * 128);
        cp_commit();
    }
    cp_wait0();
    __syncthreads();
    #pragma unroll
    for (int m = 0; m < 4; m++)
        ldm4(aBase + offA0[m], afr[0][m][0], afr[0][m][1], afr[0][m][2], afr[0][m][3]);
    #pragma unroll
    for (int p = 0; p < 2; p++)
        ldm4(bBase + offB0[p], bfr[0][2*p][0], bfr[0][2*p][1], bfr[0][2*p+1][0], bfr[0][2*p+1][1]);

    #pragma unroll
    for (int kt = 0; kt < NT; kt++) {
        const uint32_t aS = aBase + (kt % NSTG) * A_ST;
        const uint32_t bS = bBase + (kt % NSTG) * B_ST;
        const uint32_t aN = aBase + ((kt + 1) % NSTG) * A_ST;   // next stage (data already resident)
        const uint32_t bN = bBase + ((kt + 1) % NSTG) * B_ST;

        #pragma unroll
        for (int ks = 0; ks < 4; ks++) {
            const int cur = ks & 1;
            const int nxt = cur ^ 1;
            if (ks < 3) {
                const uint32_t kx = (ks + 1) * 32;
                #pragma unroll
                for (int m = 0; m < 4; m++)
                    ldm4(aS + (offA0[m] ^ kx), afr[nxt][m][0], afr[nxt][m][1],
                         afr[nxt][m][2], afr[nxt][m][3]);
                #pragma unroll
                for (int p = 0; p < 2; p++)
                    ldm4(bS + (offB0[p] ^ kx), bfr[nxt][2*p][0], bfr[nxt][2*p][1],
                         bfr[nxt][2*p+1][0], bfr[nxt][2*p+1][1]);
            } else if (kt + 1 < NT) {
                // cross-iteration prefetch: ks=0 fragments of stage kt+1 (published
                // by bottom-of-(kt-1) wait_group 0 + barrier)
                #pragma unroll
                for (int m = 0; m < 4; m++)
                    ldm4(aN + offA0[m], afr[nxt][m][0], afr[nxt][m][1],
                         afr[nxt][m][2], afr[nxt][m][3]);
                #pragma unroll
                for (int p = 0; p < 2; p++)
                    ldm4(bN + offB0[p], bfr[nxt][2*p][0], bfr[nxt][2*p][1],
                         bfr[nxt][2*p+1][0], bfr[nxt][2*p+1][1]);
            }
            #pragma unroll
            for (int m = 0; m < 4; m++)
                #pragma unroll
                for (int n = 0; n < 4; n++)
                    mma16816(c[m][n], afr[cur][m], bfr[cur][n]);

            // issue next-stage global prefetch after ks0's MMAs (LDSM-priority)
            if (ks == 0 && kt + 2 < NT) {
                const int s = (kt + 2) % NSTG;
                #pragma unroll
                for (int l = 0; l < 4; l++) cpasync16(aBase + s * A_ST + dstA[l], srcA[l] + (kt + 2) * 128);
                #pragma unroll
                for (int l = 0; l < 4; l++) cpasync16(bBase + s * B_ST + dstA[l], srcB[l] + (kt + 2) * 128);
                cp_commit();
            }
        }

        if (kt + 1 < NT) {
            cp_wait0();          // stage kt+2 resident (issued ~1 iter ago)
            __syncthreads();     // publish + protect stage reuse
        }
    }

    // ---- epilogue: exp + per-row (total, masked) partial sums ----
    int qtv[8];
    if (otile) {
        #pragma unroll
        for (int n = 0; n < 4; n++)
            #pragma unroll
            for (int e = 0; e < 2; e++)
                qtv[n * 2 + e] = qtp[wn * 32 + n * 8 + lm4 * 2 + e];
    }
    #pragma unroll
    for (int m = 0; m < 4; m++) {
        #pragma unroll
        for (int half = 0; half < 2; half++) {
            const int rl = wm * 64 + m * 16 + half * 8 + l4;   // local row
            const int tg = tgr[m * 2 + half];
            float s = 0.f, mk = 0.f;
            #pragma unroll
            for (int n = 0; n < 4; n++) {
                #pragma unroll
                for (int e = 0; e < 2; e++) {
                    float ex = __expf(fmaf(4.f, c[m][n][half * 2 + e], -4.f));
                    s += ex;
                    if (otile && qtv[n * 2 + e] == tg) mk += ex;
                }
            }
            s  += __shfl_xor_sync(0xffffffffu, s, 1);
            s  += __shfl_xor_sync(0xffffffffu, s, 2);
            mk += __shfl_xor_sync(0xffffffffu, mk, 1);
            mk += __shfl_xor_sync(0xffffffffu, mk, 2);
            if (lm4 == 0) {
                sm_s[rl * RED_PITCH + wn] = s;
                sm_m[rl * RED_PITCH + wn] = mk;
            }
        }
    }
    __syncthreads();
    if (tid < BM) {
        float tot = 0.f, msk = 0.f;
        #pragma unroll
        for (int w = 0; w < 4; w++) {
            tot += sm_s[tid * RED_PITCH + w];
            msk += sm_m[tid * RED_PITCH + w];
        }
        g_pt[blockIdx.x * N_ROWS + i0 + tid] = tot;
        g_pm[blockIdx.x * N_ROWS + i0 + tid] = msk;
    }
}

// ---------------- k_rows: per-row log terms + final reduction (ticketed) ----
__global__ void k_rows(const void* __restrict__ targets, float* __restrict__ out) {
    const int tid = threadIdx.x;
    const int i = blockIdx.x * 256 + tid;            // 8 x 256 = 2048
    float t0 = 0.f, t1 = 0.f, m0 = 0.f, m1 = 0.f;
    #pragma unroll 4
    for (int t = 0; t < NJT; t += 2) {
        t0 += g_pt[t * N_ROWS + i];
        t1 += g_pt[(t + 1) * N_ROWS + i];
        m0 += g_pm[t * N_ROWS + i];
        m1 += g_pm[(t + 1) * N_ROWS + i];
    }
    int tg = load_tgt(targets, i, g_meta[0]);
    int cnti = QK;
    #pragma unroll
    for (int b = 0; b < NHB; b++) cnti -= g_hpart[b * NCLS + tg];
    float cnt = (float)cnti;
    g_row[i] = logf(((t0 + t1) - (m0 + m1)) / cnt);

    // ticket: last block performs the deterministic final sum
    __threadfence();
    __syncthreads();
    __shared__ int amLast;
    if (tid == 0) amLast = (atomicAdd(&g_tick, 1) == (N_ROWS / 256) - 1);
    __syncthreads();
    if (amLast) {
        __shared__ float red[256];
        float s = 0.f;
        for (int k = tid; k < N_ROWS; k += 256) s += g_row[k];
        red[tid] = s;
        __syncthreads();
        for (int st = 128; st > 0; st >>= 1) {
            if (tid < st) red[tid] += red[tid + st];
            __syncthreads();
        }
        if (tid == 0) { out[0] = red[0] / (float)N_ROWS; g_tick = 0; }
    }
}

// ---------------- launch ----------------
extern "C" void kernel_launch(void* const* d_in, const int* in_sizes, int n_in,
                              void* d_out, int out_size) {
    const float* x       = (const float*)d_in[0];
    const float* q       = (const float*)d_in[1];
    const void*  targets = d_in[2];
    const void*  q_tgts  = d_in[3];
    const void*  order_p = d_in[4];

    cudaFuncSetAttribute(k_main, cudaFuncAttributeMaxDynamicSharedMemorySize, SMEM_BYTES);

    k_pre<<<NHB + 1, 256>>>(targets, q_tgts, order_p);
    {
        int total_warps = N_ROWS + QK;              // 26624
        int blocks = (total_warps + 7) / 8;
        k_convert<<<blocks, 256>>>(x, q);
    }
    dim3 grid(NJT, N_ROWS / BM);                    // 192 x 16
    k_main<<<grid, 256, SMEM_BYTES>>>(targets, q_tgts);
    k_rows<<<N_ROWS / 256, 256>>>(targets, (float*)d_out);
}